// round 10
// baseline (speedup 1.0000x reference)
#include <cuda_runtime.h>
#include <cuda_bf16.h>
#include <cstdint>

#define NN    32768
#define FIN   256
#define HH    4
#define CC    128
#define HC    512
#define EMAX  524288
#define NEG   0.2f

// ---------------- scratch ----------------
__device__ float g_h[(size_t)NN * HC];     // post-GEMM features fp32
__device__ float g_t[(size_t)NN * CC];
__device__ float g_asrc[NN * HH];
__device__ float g_adst[NN * HH];
__device__ float4 g_ew[EMAX + NN];         // per-edge unnormalized weights
__device__ float4 g_dinv[NN];              // per-node inverse denominators
__device__ int   g_deg[NN];
__device__ int   g_rowptr[NN + 1];
__device__ int   g_cursor[NN];
__device__ int   g_csr[EMAX + NN];
__device__ float g_bnsum[CC];
__device__ float g_bnsq[CC];
__device__ float g_scale[CC];
__device__ float g_shift[CC];
__device__ int   g_is64;
__device__ int   g_bsum[128];
__device__ __nv_bfloat16 g_Bhi[HC * FIN];
__device__ __nv_bfloat16 g_Blo[HC * FIN];
__device__ __nv_bfloat16 g_Ahi[(size_t)NN * FIN];
__device__ __nv_bfloat16 g_Alo[(size_t)NN * FIN];

__device__ __forceinline__ uint32_t smem_u32(const void* p) {
    uint32_t a;
    asm("{ .reg .u64 t; cvta.to.shared.u64 t, %1; cvt.u32.u64 %0, t; }" : "=r"(a) : "l"(p));
    return a;
}
#define LDSM_X4(r0, r1, r2, r3, addr) \
    asm volatile("ldmatrix.sync.aligned.m8n8.x4.shared.b16 {%0,%1,%2,%3}, [%4];" \
        : "=r"(r0), "=r"(r1), "=r"(r2), "=r"(r3) : "r"(addr))
#define MMA16816(d, a0, a1, a2, a3, b0, b1) \
    asm volatile("mma.sync.aligned.m16n8k16.row.col.f32.bf16.bf16.f32 " \
        "{%0,%1,%2,%3},{%4,%5,%6,%7},{%8,%9},{%0,%1,%2,%3};" \
        : "+f"((d)[0]), "+f"((d)[1]), "+f"((d)[2]), "+f"((d)[3]) \
        : "r"(a0), "r"(a1), "r"(a2), "r"(a3), "r"(b0), "r"(b1))
__device__ __forceinline__ void cp16(uint32_t dst, const void* src) {
    asm volatile("cp.async.cg.shared.global [%0], [%1], 16;" :: "r"(dst), "l"(src));
}
#define CP_COMMIT() asm volatile("cp.async.commit_group;" ::: "memory")

__device__ __forceinline__ int edge_at(const void* ei, int is64, size_t idx) {
    return is64 ? (int)((const long long*)ei)[idx] : ((const int*)ei)[idx];
}

// ---------------- init + dtype detection (merged) ----------------
__global__ void k_initdet(const unsigned int* __restrict__ ei32) {
    __shared__ unsigned int s_or[256];
    int i = blockIdx.x * blockDim.x + threadIdx.x;
    if (i < NN) g_deg[i] = 1;
    if (i < CC) { g_bnsum[i] = 0.f; g_bnsq[i] = 0.f; }
    if (blockIdx.x == 0) {
        unsigned int v = 0;
        int t = threadIdx.x;
#pragma unroll
        for (int k = 0; k < 8; k++) v |= ei32[2 * (t * 8 + k) + 1];
        s_or[t] = v;
        __syncthreads();
        for (int o = 128; o > 0; o >>= 1) {
            if (t < o) s_or[t] |= s_or[t + o];
            __syncthreads();
        }
        if (t == 0) g_is64 = (s_or[0] == 0) ? 1 : 0;
    }
}

// ---------------- CSR build ----------------
__global__ void k_hist(const void* __restrict__ ei, int E) {
    int e = blockIdx.x * blockDim.x + threadIdx.x;
    int is64 = g_is64;
    if (e < E) atomicAdd(&g_deg[edge_at(ei, is64, (size_t)E + e)], 1);
}
__global__ void k_scan1() {
    __shared__ int s[256];
    int b = blockIdx.x, t = threadIdx.x;
    s[t] = g_deg[b * 256 + t];
    __syncthreads();
    for (int o = 128; o > 0; o >>= 1) {
        if (t < o) s[t] += s[t + o];
        __syncthreads();
    }
    if (t == 0) g_bsum[b] = s[0];
}
__global__ void k_scan2() {
    __shared__ int s[128];
    int t = threadIdx.x;
    int v = g_bsum[t];
    s[t] = v;
    __syncthreads();
    for (int off = 1; off < 128; off <<= 1) {
        int x = (t >= off) ? s[t - off] : 0;
        __syncthreads();
        s[t] += x;
        __syncthreads();
    }
    g_bsum[t] = s[t] - v;
    if (t == 127) g_rowptr[NN] = s[127];
}
__global__ void k_scan3() {
    __shared__ int s[256];
    int b = blockIdx.x, t = threadIdx.x;
    int i = b * 256 + t;
    int v = g_deg[i];
    s[t] = v;
    __syncthreads();
    for (int off = 1; off < 256; off <<= 1) {
        int x = (t >= off) ? s[t - off] : 0;
        __syncthreads();
        s[t] += x;
        __syncthreads();
    }
    int excl = s[t] - v + g_bsum[b];
    g_rowptr[i] = excl;
    g_cursor[i] = excl;
}
__global__ void k_scatter(const void* __restrict__ ei, int E) {
    int e = blockIdx.x * blockDim.x + threadIdx.x;
    int is64 = g_is64;
    if (e < E) {
        int s = edge_at(ei, is64, e);
        int d = edge_at(ei, is64, (size_t)E + e);
        g_csr[atomicAdd(&g_cursor[d], 1)] = s;
    } else if (e < E + NN) {
        int n = e - E;
        g_csr[atomicAdd(&g_cursor[n], 1)] = n;
    }
}

// ---------------- weight pretranspose + split ----------------
__global__ void k_prep(const float* __restrict__ W, int K, int Nn) {
    __shared__ float tile[32][33];
    int nb = blockIdx.x * 32, kb = blockIdx.y * 32;
    for (int j = threadIdx.y; j < 32; j += 8)
        tile[j][threadIdx.x] = W[(size_t)(kb + j) * Nn + nb + threadIdx.x];
    __syncthreads();
    for (int j = threadIdx.y; j < 32; j += 8) {
        float v = tile[threadIdx.x][j];
        __nv_bfloat16 hi = __float2bfloat16_rn(v);
        __nv_bfloat16 lo = __float2bfloat16_rn(v - __bfloat162float(hi));
        size_t o = (size_t)(nb + j) * K + kb + threadIdx.x;
        g_Bhi[o] = hi;
        g_Blo[o] = lo;
    }
}

// ---------------- activation conversion (BN+ReLU fused) -> bf16 hi/lo --------
template <bool FUSE>
__global__ void k_conv(const float4* __restrict__ src, int kmask4) {
    int i = blockIdx.x * blockDim.x + threadIdx.x;
    if (i < NN * HH) { g_asrc[i] = 0.f; g_adst[i] = 0.f; }
    float4 v = src[i];
    if (FUSE) {
        int ch = (i & kmask4) * 4;
        v.x = fmaxf(fmaf(v.x, g_scale[ch + 0], g_shift[ch + 0]), 0.f);
        v.y = fmaxf(fmaf(v.y, g_scale[ch + 1], g_shift[ch + 1]), 0.f);
        v.z = fmaxf(fmaf(v.z, g_scale[ch + 2], g_shift[ch + 2]), 0.f);
        v.w = fmaxf(fmaf(v.w, g_scale[ch + 3], g_shift[ch + 3]), 0.f);
    }
    __nv_bfloat162 h0 = __floats2bfloat162_rn(v.x, v.y);
    __nv_bfloat162 h1 = __floats2bfloat162_rn(v.z, v.w);
    __nv_bfloat162 l0 = __floats2bfloat162_rn(v.x - __bfloat162float(h0.x),
                                              v.y - __bfloat162float(h0.y));
    __nv_bfloat162 l1 = __floats2bfloat162_rn(v.z - __bfloat162float(h1.x),
                                              v.w - __bfloat162float(h1.y));
    *(uint2*)&g_Ahi[(size_t)i * 4] = make_uint2(*(uint32_t*)&h0, *(uint32_t*)&h1);
    *(uint2*)&g_Alo[(size_t)i * 4] = make_uint2(*(uint32_t*)&l0, *(uint32_t*)&l1);
}

// ---------------- cp.async double-buffered bf16 mma GEMM ----------------
template <int K, bool ATTN, bool BIAS>
__global__ void __launch_bounds__(256) k_gemm_m(
    float* __restrict__ C, int Nn,
    const float* __restrict__ attS, const float* __restrict__ attD,
    const float* __restrict__ bias)
{
    constexpr int NC = K / 32;
    constexpr uint32_t STG = 40960;
    constexpr uint32_t OFF_AL = 10240, OFF_BH = 20480, OFF_BL = 30720;
    extern __shared__ __align__(16) char smraw[];
    const uint32_t sb = smem_u32(smraw);

    const int tid = threadIdx.x;
    const int lane = tid & 31;
    const int wid = tid >> 5;
    const int wm = wid & 3, wn = wid >> 2;
    const int row0 = blockIdx.y * 128, col0 = blockIdx.x * 128;

    float d[2][8][4];
#pragma unroll
    for (int i = 0; i < 2; i++)
#pragma unroll
        for (int j = 0; j < 8; j++)
#pragma unroll
            for (int q = 0; q < 4; q++) d[i][j][q] = 0.f;

    const int c0 = tid, c1 = tid + 256;
    const int r0s = c0 >> 2, kb0 = c0 & 3;
    const int r1s = c1 >> 2, kb1 = c1 & 3;

#define STAGE(kc, s) do { \
    uint32_t b = sb + (s) * STG; \
    cp16(b + r0s * 80 + kb0 * 16, &g_Ahi[(size_t)(row0 + r0s) * K + (kc) * 32 + kb0 * 8]); \
    cp16(b + r1s * 80 + kb1 * 16, &g_Ahi[(size_t)(row0 + r1s) * K + (kc) * 32 + kb1 * 8]); \
    cp16(b + OFF_AL + r0s * 80 + kb0 * 16, &g_Alo[(size_t)(row0 + r0s) * K + (kc) * 32 + kb0 * 8]); \
    cp16(b + OFF_AL + r1s * 80 + kb1 * 16, &g_Alo[(size_t)(row0 + r1s) * K + (kc) * 32 + kb1 * 8]); \
    cp16(b + OFF_BH + r0s * 80 + kb0 * 16, &g_Bhi[(size_t)(col0 + r0s) * K + (kc) * 32 + kb0 * 8]); \
    cp16(b + OFF_BH + r1s * 80 + kb1 * 16, &g_Bhi[(size_t)(col0 + r1s) * K + (kc) * 32 + kb1 * 8]); \
    cp16(b + OFF_BL + r0s * 80 + kb0 * 16, &g_Blo[(size_t)(col0 + r0s) * K + (kc) * 32 + kb0 * 8]); \
    cp16(b + OFF_BL + r1s * 80 + kb1 * 16, &g_Blo[(size_t)(col0 + r1s) * K + (kc) * 32 + kb1 * 8]); \
} while (0)

    STAGE(0, 0);
    CP_COMMIT();

    const int a_row = lane & 15, a_col8 = (lane >> 4) * 8;
    const int b_row = ((lane >> 4) << 3) + (lane & 7), b_col8 = ((lane >> 3) & 1) * 8;

    for (int kc = 0; kc < NC; ++kc) {
        if (kc + 1 < NC) {
            STAGE(kc + 1, (kc + 1) & 1);
            CP_COMMIT();
            asm volatile("cp.async.wait_group 1;" ::: "memory");
        } else {
            asm volatile("cp.async.wait_group 0;" ::: "memory");
        }
        __syncthreads();

        const uint32_t bs = sb + (kc & 1) * STG;
#pragma unroll
        for (int kk = 0; kk < 32; kk += 16) {
            uint32_t ah[2][4], al[2][4], bh[8][2], bl[8][2];
#pragma unroll
            for (int mi = 0; mi < 2; mi++) {
                uint32_t off = (uint32_t)((wm * 32 + mi * 16 + a_row) * 40 + kk + a_col8) * 2;
                LDSM_X4(ah[mi][0], ah[mi][1], ah[mi][2], ah[mi][3], bs + off);
                LDSM_X4(al[mi][0], al[mi][1], al[mi][2], al[mi][3], bs + OFF_AL + off);
            }
#pragma unroll
            for (int np = 0; np < 4; np++) {
                uint32_t off = (uint32_t)((wn * 64 + np * 16 + b_row) * 40 + kk + b_col8) * 2;
                uint32_t r0, r1, r2, r3;
                LDSM_X4(r0, r1, r2, r3, bs + OFF_BH + off);
                bh[np * 2][0] = r0; bh[np * 2][1] = r1;
                bh[np * 2 + 1][0] = r2; bh[np * 2 + 1][1] = r3;
                LDSM_X4(r0, r1, r2, r3, bs + OFF_BL + off);
                bl[np * 2][0] = r0; bl[np * 2][1] = r1;
                bl[np * 2 + 1][0] = r2; bl[np * 2 + 1][1] = r3;
            }
#pragma unroll
            for (int mi = 0; mi < 2; mi++)
#pragma unroll
                for (int ni = 0; ni < 8; ni++) {
                    MMA16816(d[mi][ni], ah[mi][0], ah[mi][1], ah[mi][2], ah[mi][3],
                             bh[ni][0], bh[ni][1]);
                    MMA16816(d[mi][ni], ah[mi][0], ah[mi][1], ah[mi][2], ah[mi][3],
                             bl[ni][0], bl[ni][1]);
                    MMA16816(d[mi][ni], al[mi][0], al[mi][1], al[mi][2], al[mi][3],
                             bh[ni][0], bh[ni][1]);
                }
        }
        __syncthreads();
    }
#undef STAGE

    const int er = lane >> 2, ec = (lane & 3) * 2;
#pragma unroll
    for (int mi = 0; mi < 2; mi++) {
        float s0 = 0.f, s1 = 0.f, t0 = 0.f, t1 = 0.f;
#pragma unroll
        for (int ni = 0; ni < 8; ni++) {
            int r = row0 + wm * 32 + mi * 16 + er;
            int c = col0 + wn * 64 + ni * 8 + ec;
            float2 v0 = make_float2(d[mi][ni][0], d[mi][ni][1]);
            float2 v1 = make_float2(d[mi][ni][2], d[mi][ni][3]);
            if (BIAS) {
                float b0 = __ldg(&bias[c]), b1 = __ldg(&bias[c + 1]);
                v0.x += b0; v0.y += b1; v1.x += b0; v1.y += b1;
            }
            if (ATTN) {
                int cc = wn * 64 + ni * 8 + ec;
                int head = blockIdx.x;
                float a0 = __ldg(&attS[head * CC + cc]);
                float a1 = __ldg(&attS[head * CC + cc + 1]);
                float e0 = __ldg(&attD[head * CC + cc]);
                float e1 = __ldg(&attD[head * CC + cc + 1]);
                s0 = fmaf(v0.x, a0, fmaf(v0.y, a1, s0));
                s1 = fmaf(v1.x, a0, fmaf(v1.y, a1, s1));
                t0 = fmaf(v0.x, e0, fmaf(v0.y, e1, t0));
                t1 = fmaf(v1.x, e0, fmaf(v1.y, e1, t1));
            }
            *(float2*)&C[(size_t)r * Nn + c] = v0;
            *(float2*)&C[(size_t)(r + 8) * Nn + c] = v1;
        }
        if (ATTN) {
            s0 += __shfl_xor_sync(0xffffffffu, s0, 1);
            s0 += __shfl_xor_sync(0xffffffffu, s0, 2);
            s1 += __shfl_xor_sync(0xffffffffu, s1, 1);
            s1 += __shfl_xor_sync(0xffffffffu, s1, 2);
            t0 += __shfl_xor_sync(0xffffffffu, t0, 1);
            t0 += __shfl_xor_sync(0xffffffffu, t0, 2);
            t1 += __shfl_xor_sync(0xffffffffu, t1, 1);
            t1 += __shfl_xor_sync(0xffffffffu, t1, 2);
            if ((lane & 3) == 0) {
                int head = blockIdx.x;
                int r = row0 + wm * 32 + mi * 16 + er;
                atomicAdd(&g_asrc[r * 4 + head], s0);
                atomicAdd(&g_adst[r * 4 + head], t0);
                atomicAdd(&g_asrc[(r + 8) * 4 + head], s1);
                atomicAdd(&g_adst[(r + 8) * 4 + head], t1);
            }
        }
    }
}

__device__ __forceinline__ float lrelu(float v) { return v > 0.f ? v : NEG * v; }

// ---------------- per-edge weights (lane-parallel, one exp per edge-head) ----
// warp per dst node; lanes over edges. Stores unnormalized w (float4) per edge
// and inverse denominators per node. Softmax shift dropped (logits bounded).
__global__ void __launch_bounds__(256) k_edgew() {
    int lane = threadIdx.x & 31;
    int n = blockIdx.x * 8 + (threadIdx.x >> 5);
    int start = g_rowptr[n], end = g_rowptr[n + 1];
    float4 ad = *(const float4*)&g_adst[n * 4];

    float d0 = 0.f, d1 = 0.f, d2 = 0.f, d3 = 0.f;
    for (int i = start + lane; i < end; i += 32) {
        int s = g_csr[i];
        float4 as = *(const float4*)&g_asrc[s * 4];
        float w0 = __expf(lrelu(as.x + ad.x));
        float w1 = __expf(lrelu(as.y + ad.y));
        float w2 = __expf(lrelu(as.z + ad.z));
        float w3 = __expf(lrelu(as.w + ad.w));
        g_ew[i] = make_float4(w0, w1, w2, w3);
        d0 += w0; d1 += w1; d2 += w2; d3 += w3;
    }
#pragma unroll
    for (int o = 16; o > 0; o >>= 1) {
        d0 += __shfl_xor_sync(0xffffffffu, d0, o);
        d1 += __shfl_xor_sync(0xffffffffu, d1, o);
        d2 += __shfl_xor_sync(0xffffffffu, d2, o);
        d3 += __shfl_xor_sync(0xffffffffu, d3, o);
    }
    if (lane == 0)
        g_dinv[n] = make_float4(1.f / (d0 + 1e-16f), 1.f / (d1 + 1e-16f),
                                1.f / (d2 + 1e-16f), 1.f / (d3 + 1e-16f));
}

// ---------------- aggregation: lean weighted gather (warp per node) ----------
__global__ void __launch_bounds__(256) k_aggr(const float* __restrict__ h,
                                              const float* __restrict__ bias)
{
    __shared__ float s_sum[CC], s_sq[CC];
    int tid = threadIdx.x;
    if (tid < CC) { s_sum[tid] = 0.f; s_sq[tid] = 0.f; }
    __syncthreads();

    int lane = tid & 31;
    int n = blockIdx.x * 8 + (tid >> 5);
    int start = g_rowptr[n], end = g_rowptr[n + 1];

    const float4* hp = (const float4*)h;
    float4 a0 = make_float4(0.f, 0.f, 0.f, 0.f), a1 = a0, a2 = a0, a3 = a0;
    for (int i = start; i < end; ++i) {
        int s = g_csr[i];
        float4 w = g_ew[i];
        size_t base = (size_t)s * 128;
        float4 v;
        v = hp[base + lane];
        a0.x = fmaf(v.x, w.x, a0.x); a0.y = fmaf(v.y, w.x, a0.y);
        a0.z = fmaf(v.z, w.x, a0.z); a0.w = fmaf(v.w, w.x, a0.w);
        v = hp[base + 32 + lane];
        a1.x = fmaf(v.x, w.y, a1.x); a1.y = fmaf(v.y, w.y, a1.y);
        a1.z = fmaf(v.z, w.y, a1.z); a1.w = fmaf(v.w, w.y, a1.w);
        v = hp[base + 64 + lane];
        a2.x = fmaf(v.x, w.z, a2.x); a2.y = fmaf(v.y, w.z, a2.y);
        a2.z = fmaf(v.z, w.z, a2.z); a2.w = fmaf(v.w, w.z, a2.w);
        v = hp[base + 96 + lane];
        a3.x = fmaf(v.x, w.w, a3.x); a3.y = fmaf(v.y, w.w, a3.y);
        a3.z = fmaf(v.z, w.w, a3.z); a3.w = fmaf(v.w, w.w, a3.w);
    }
    float4 inv = g_dinv[n];

    float4 bb = ((const float4*)bias)[lane];
    float4 o;
    o.x = 0.25f * (a0.x * inv.x + a1.x * inv.y + a2.x * inv.z + a3.x * inv.w) + bb.x;
    o.y = 0.25f * (a0.y * inv.x + a1.y * inv.y + a2.y * inv.z + a3.y * inv.w) + bb.y;
    o.z = 0.25f * (a0.z * inv.x + a1.z * inv.y + a2.z * inv.z + a3.z * inv.w) + bb.z;
    o.w = 0.25f * (a0.w * inv.x + a1.w * inv.y + a2.w * inv.z + a3.w * inv.w) + bb.w;
    ((float4*)g_t)[(size_t)n * 32 + lane] = o;

    int c = lane * 4;
    atomicAdd(&s_sum[c + 0], o.x); atomicAdd(&s_sq[c + 0], o.x * o.x);
    atomicAdd(&s_sum[c + 1], o.y); atomicAdd(&s_sq[c + 1], o.y * o.y);
    atomicAdd(&s_sum[c + 2], o.z); atomicAdd(&s_sq[c + 2], o.z * o.z);
    atomicAdd(&s_sum[c + 3], o.w); atomicAdd(&s_sq[c + 3], o.w * o.w);
    __syncthreads();
    if (tid < CC) {
        atomicAdd(&g_bnsum[tid], s_sum[tid]);
        atomicAdd(&g_bnsq[tid], s_sq[tid]);
    }
}

__global__ void k_bnfin(const float* __restrict__ g, const float* __restrict__ be) {
    int c = threadIdx.x;
    float mu = g_bnsum[c] * (1.f / NN);
    float var = g_bnsq[c] * (1.f / NN) - mu * mu;
    float sc = g[c] * rsqrtf(var + 1e-5f);
    g_scale[c] = sc;
    g_shift[c] = be[c] - mu * sc;
    g_bnsum[c] = 0.f;
    g_bnsq[c] = 0.f;
}

// ---------------- launch ----------------
extern "C" void kernel_launch(void* const* d_in, const int* in_sizes, int n_in,
                              void* d_out, int out_size)
{
    const float* x   = (const float*)d_in[0];
    const void*  ei  = d_in[1];
    const float* W1  = (const float*)d_in[2];
    const float* as1 = (const float*)d_in[3];
    const float* ad1 = (const float*)d_in[4];
    const float* b1  = (const float*)d_in[5];
    const float* g1  = (const float*)d_in[6];
    const float* be1 = (const float*)d_in[7];
    const float* W2  = (const float*)d_in[8];
    const float* as2 = (const float*)d_in[9];
    const float* ad2 = (const float*)d_in[10];
    const float* b2  = (const float*)d_in[11];
    const float* g2  = (const float*)d_in[12];
    const float* be2 = (const float*)d_in[13];
    const float* Wf  = (const float*)d_in[14];
    const float* bf  = (const float*)d_in[15];
    int E = in_sizes[1] / 2;

    float *ph = nullptr, *pt = nullptr;
    cudaGetSymbolAddress((void**)&ph, g_h);
    cudaGetSymbolAddress((void**)&pt, g_t);
    float* out = (float*)d_out;

    constexpr int SMEM = 81920;
    cudaFuncSetAttribute(k_gemm_m<256, true, false>,
                         cudaFuncAttributeMaxDynamicSharedMemorySize, SMEM);
    cudaFuncSetAttribute(k_gemm_m<128, true, false>,
                         cudaFuncAttributeMaxDynamicSharedMemorySize, SMEM);
    cudaFuncSetAttribute(k_gemm_m<128, false, true>,
                         cudaFuncAttributeMaxDynamicSharedMemorySize, SMEM);

    // layer-1 GEMM chain
    k_prep<<<dim3(HC / 32, FIN / 32), dim3(32, 8)>>>(W1, FIN, HC);
    k_conv<false><<<NN * FIN / 1024, 256>>>((const float4*)x, FIN / 4 - 1);
    k_gemm_m<256, true, false><<<dim3(4, 256), 256, SMEM>>>(ph, HC, as1, ad1, nullptr);

    // CSR build
    k_initdet<<<NN / 256, 256>>>((const unsigned int*)ei);
    k_hist<<<(E + 255) / 256, 256>>>(ei, E);
    k_scan1<<<128, 256>>>();
    k_scan2<<<1, 128>>>();
    k_scan3<<<128, 256>>>();
    k_scatter<<<(E + NN + 255) / 256, 256>>>(ei, E);

    k_edgew<<<4096, 256>>>();
    k_aggr<<<4096, 256>>>(ph, b1);
    k_bnfin<<<1, 128>>>(g1, be1);

    // layer 2
    k_prep<<<dim3(HC / 32, CC / 32), dim3(32, 8)>>>(W2, CC, HC);
    k_conv<true><<<NN * CC / 1024, 256>>>((const float4*)pt, CC / 4 - 1);
    k_gemm_m<128, true, false><<<dim3(4, 256), 256, SMEM>>>(ph, HC, as2, ad2, nullptr);
    k_edgew<<<4096, 256>>>();
    k_aggr<<<4096, 256>>>(ph, b2);
    k_bnfin<<<1, 128>>>(g2, be2);

    // final linear (fp32 out)
    k_prep<<<dim3(CC / 32, CC / 32), dim3(32, 8)>>>(Wf, CC, CC);
    k_conv<true><<<NN * CC / 1024, 256>>>((const float4*)pt, CC / 4 - 1);
    k_gemm_m<128, false, true><<<dim3(1, 256), 256, SMEM>>>(out, CC, nullptr, nullptr, bf);
}

// round 11
// speedup vs baseline: 1.0053x; 1.0053x over previous
#include <cuda_runtime.h>
#include <cuda_bf16.h>
#include <cstdint>

#define NN    32768
#define FIN   256
#define HH    4
#define CC    128
#define HC    512
#define EMAX  524288
#define NEG   0.2f

// ---------------- scratch ----------------
__device__ float g_h[(size_t)NN * HC];     // post-GEMM features fp32
__device__ float g_t[(size_t)NN * CC];
__device__ float g_asrc[NN * HH];
__device__ float g_adst[NN * HH];
__device__ float4 g_ew[EMAX + NN];         // per-edge unnormalized weights
__device__ float4 g_dinv[NN];              // per-node inverse denominators
__device__ int   g_deg[NN];
__device__ int   g_rowptr[NN + 1];
__device__ int   g_cursor[NN];
__device__ int   g_csr[EMAX + NN];
__device__ float g_bnsum[CC];
__device__ float g_bnsq[CC];
__device__ float g_scale[CC];
__device__ float g_shift[CC];
__device__ int   g_is64;
__device__ int   g_bsum[128];
__device__ __nv_bfloat16 g_Bhi[HC * FIN];
__device__ __nv_bfloat16 g_Blo[HC * FIN];
__device__ __nv_bfloat16 g_Ahi[(size_t)NN * FIN];
__device__ __nv_bfloat16 g_Alo[(size_t)NN * FIN];

__device__ __forceinline__ uint32_t smem_u32(const void* p) {
    uint32_t a;
    asm("{ .reg .u64 t; cvta.to.shared.u64 t, %1; cvt.u32.u64 %0, t; }" : "=r"(a) : "l"(p));
    return a;
}
#define LDSM_X4(r0, r1, r2, r3, addr) \
    asm volatile("ldmatrix.sync.aligned.m8n8.x4.shared.b16 {%0,%1,%2,%3}, [%4];" \
        : "=r"(r0), "=r"(r1), "=r"(r2), "=r"(r3) : "r"(addr))
#define MMA16816(d, a0, a1, a2, a3, b0, b1) \
    asm volatile("mma.sync.aligned.m16n8k16.row.col.f32.bf16.bf16.f32 " \
        "{%0,%1,%2,%3},{%4,%5,%6,%7},{%8,%9},{%0,%1,%2,%3};" \
        : "+f"((d)[0]), "+f"((d)[1]), "+f"((d)[2]), "+f"((d)[3]) \
        : "r"(a0), "r"(a1), "r"(a2), "r"(a3), "r"(b0), "r"(b1))
__device__ __forceinline__ void cp16(uint32_t dst, const void* src) {
    asm volatile("cp.async.cg.shared.global [%0], [%1], 16;" :: "r"(dst), "l"(src));
}
#define CP_COMMIT() asm volatile("cp.async.commit_group;" ::: "memory")

__device__ __forceinline__ int edge_at(const void* ei, int is64, size_t idx) {
    return is64 ? (int)((const long long*)ei)[idx] : ((const int*)ei)[idx];
}

// ---------------- init + dtype detection (merged) ----------------
__global__ void k_initdet(const unsigned int* __restrict__ ei32) {
    __shared__ unsigned int s_or[256];
    int i = blockIdx.x * blockDim.x + threadIdx.x;
    if (i < NN) g_deg[i] = 1;
    if (i < CC) { g_bnsum[i] = 0.f; g_bnsq[i] = 0.f; }
    if (blockIdx.x == 0) {
        unsigned int v = 0;
        int t = threadIdx.x;
#pragma unroll
        for (int k = 0; k < 8; k++) v |= ei32[2 * (t * 8 + k) + 1];
        s_or[t] = v;
        __syncthreads();
        for (int o = 128; o > 0; o >>= 1) {
            if (t < o) s_or[t] |= s_or[t + o];
            __syncthreads();
        }
        if (t == 0) g_is64 = (s_or[0] == 0) ? 1 : 0;
    }
}

// ---------------- CSR build ----------------
__global__ void k_hist(const void* __restrict__ ei, int E) {
    int e = blockIdx.x * blockDim.x + threadIdx.x;
    int is64 = g_is64;
    if (e < E) atomicAdd(&g_deg[edge_at(ei, is64, (size_t)E + e)], 1);
}
__global__ void k_scan1() {
    __shared__ int s[256];
    int b = blockIdx.x, t = threadIdx.x;
    s[t] = g_deg[b * 256 + t];
    __syncthreads();
    for (int o = 128; o > 0; o >>= 1) {
        if (t < o) s[t] += s[t + o];
        __syncthreads();
    }
    if (t == 0) g_bsum[b] = s[0];
}
__global__ void k_scan2() {
    __shared__ int s[128];
    int t = threadIdx.x;
    int v = g_bsum[t];
    s[t] = v;
    __syncthreads();
    for (int off = 1; off < 128; off <<= 1) {
        int x = (t >= off) ? s[t - off] : 0;
        __syncthreads();
        s[t] += x;
        __syncthreads();
    }
    g_bsum[t] = s[t] - v;
    if (t == 127) g_rowptr[NN] = s[127];
}
__global__ void k_scan3() {
    __shared__ int s[256];
    int b = blockIdx.x, t = threadIdx.x;
    int i = b * 256 + t;
    int v = g_deg[i];
    s[t] = v;
    __syncthreads();
    for (int off = 1; off < 256; off <<= 1) {
        int x = (t >= off) ? s[t - off] : 0;
        __syncthreads();
        s[t] += x;
        __syncthreads();
    }
    int excl = s[t] - v + g_bsum[b];
    g_rowptr[i] = excl;
    g_cursor[i] = excl;
}
__global__ void k_scatter(const void* __restrict__ ei, int E) {
    int e = blockIdx.x * blockDim.x + threadIdx.x;
    int is64 = g_is64;
    if (e < E) {
        int s = edge_at(ei, is64, e);
        int d = edge_at(ei, is64, (size_t)E + e);
        g_csr[atomicAdd(&g_cursor[d], 1)] = s;
    } else if (e < E + NN) {
        int n = e - E;
        g_csr[atomicAdd(&g_cursor[n], 1)] = n;
    }
}

// ---------------- weight pretranspose + split ----------------
__global__ void k_prep(const float* __restrict__ W, int K, int Nn) {
    __shared__ float tile[32][33];
    int nb = blockIdx.x * 32, kb = blockIdx.y * 32;
    for (int j = threadIdx.y; j < 32; j += 8)
        tile[j][threadIdx.x] = W[(size_t)(kb + j) * Nn + nb + threadIdx.x];
    __syncthreads();
    for (int j = threadIdx.y; j < 32; j += 8) {
        float v = tile[threadIdx.x][j];
        __nv_bfloat16 hi = __float2bfloat16_rn(v);
        __nv_bfloat16 lo = __float2bfloat16_rn(v - __bfloat162float(hi));
        size_t o = (size_t)(nb + j) * K + kb + threadIdx.x;
        g_Bhi[o] = hi;
        g_Blo[o] = lo;
    }
}

// ---------------- activation conversion (BN+ReLU fused) -> bf16 hi/lo --------
template <bool FUSE>
__global__ void k_conv(const float4* __restrict__ src, int kmask4) {
    int i = blockIdx.x * blockDim.x + threadIdx.x;
    if (i < NN * HH) { g_asrc[i] = 0.f; g_adst[i] = 0.f; }
    float4 v = src[i];
    if (FUSE) {
        int ch = (i & kmask4) * 4;
        v.x = fmaxf(fmaf(v.x, g_scale[ch + 0], g_shift[ch + 0]), 0.f);
        v.y = fmaxf(fmaf(v.y, g_scale[ch + 1], g_shift[ch + 1]), 0.f);
        v.z = fmaxf(fmaf(v.z, g_scale[ch + 2], g_shift[ch + 2]), 0.f);
        v.w = fmaxf(fmaf(v.w, g_scale[ch + 3], g_shift[ch + 3]), 0.f);
    }
    __nv_bfloat162 h0 = __floats2bfloat162_rn(v.x, v.y);
    __nv_bfloat162 h1 = __floats2bfloat162_rn(v.z, v.w);
    __nv_bfloat162 l0 = __floats2bfloat162_rn(v.x - __bfloat162float(h0.x),
                                              v.y - __bfloat162float(h0.y));
    __nv_bfloat162 l1 = __floats2bfloat162_rn(v.z - __bfloat162float(h1.x),
                                              v.w - __bfloat162float(h1.y));
    *(uint2*)&g_Ahi[(size_t)i * 4] = make_uint2(*(uint32_t*)&h0, *(uint32_t*)&h1);
    *(uint2*)&g_Alo[(size_t)i * 4] = make_uint2(*(uint32_t*)&l0, *(uint32_t*)&l1);
}

// ---------------- cp.async double-buffered bf16 mma GEMM ----------------
template <int K, bool ATTN, bool BIAS>
__global__ void __launch_bounds__(256) k_gemm_m(
    float* __restrict__ C, int Nn,
    const float* __restrict__ attS, const float* __restrict__ attD,
    const float* __restrict__ bias)
{
    constexpr int NC = K / 32;
    constexpr uint32_t STG = 40960;
    constexpr uint32_t OFF_AL = 10240, OFF_BH = 20480, OFF_BL = 30720;
    extern __shared__ __align__(16) char smraw[];
    const uint32_t sb = smem_u32(smraw);

    const int tid = threadIdx.x;
    const int lane = tid & 31;
    const int wid = tid >> 5;
    const int wm = wid & 3, wn = wid >> 2;
    const int row0 = blockIdx.y * 128, col0 = blockIdx.x * 128;

    float d[2][8][4];
#pragma unroll
    for (int i = 0; i < 2; i++)
#pragma unroll
        for (int j = 0; j < 8; j++)
#pragma unroll
            for (int q = 0; q < 4; q++) d[i][j][q] = 0.f;

    const int c0 = tid, c1 = tid + 256;
    const int r0s = c0 >> 2, kb0 = c0 & 3;
    const int r1s = c1 >> 2, kb1 = c1 & 3;

#define STAGE(kc, s) do { \
    uint32_t b = sb + (s) * STG; \
    cp16(b + r0s * 80 + kb0 * 16, &g_Ahi[(size_t)(row0 + r0s) * K + (kc) * 32 + kb0 * 8]); \
    cp16(b + r1s * 80 + kb1 * 16, &g_Ahi[(size_t)(row0 + r1s) * K + (kc) * 32 + kb1 * 8]); \
    cp16(b + OFF_AL + r0s * 80 + kb0 * 16, &g_Alo[(size_t)(row0 + r0s) * K + (kc) * 32 + kb0 * 8]); \
    cp16(b + OFF_AL + r1s * 80 + kb1 * 16, &g_Alo[(size_t)(row0 + r1s) * K + (kc) * 32 + kb1 * 8]); \
    cp16(b + OFF_BH + r0s * 80 + kb0 * 16, &g_Bhi[(size_t)(col0 + r0s) * K + (kc) * 32 + kb0 * 8]); \
    cp16(b + OFF_BH + r1s * 80 + kb1 * 16, &g_Bhi[(size_t)(col0 + r1s) * K + (kc) * 32 + kb1 * 8]); \
    cp16(b + OFF_BL + r0s * 80 + kb0 * 16, &g_Blo[(size_t)(col0 + r0s) * K + (kc) * 32 + kb0 * 8]); \
    cp16(b + OFF_BL + r1s * 80 + kb1 * 16, &g_Blo[(size_t)(col0 + r1s) * K + (kc) * 32 + kb1 * 8]); \
} while (0)

    STAGE(0, 0);
    CP_COMMIT();

    const int a_row = lane & 15, a_col8 = (lane >> 4) * 8;
    const int b_row = ((lane >> 4) << 3) + (lane & 7), b_col8 = ((lane >> 3) & 1) * 8;

    for (int kc = 0; kc < NC; ++kc) {
        if (kc + 1 < NC) {
            STAGE(kc + 1, (kc + 1) & 1);
            CP_COMMIT();
            asm volatile("cp.async.wait_group 1;" ::: "memory");
        } else {
            asm volatile("cp.async.wait_group 0;" ::: "memory");
        }
        __syncthreads();

        const uint32_t bs = sb + (kc & 1) * STG;
#pragma unroll
        for (int kk = 0; kk < 32; kk += 16) {
            uint32_t ah[2][4], al[2][4], bh[8][2], bl[8][2];
#pragma unroll
            for (int mi = 0; mi < 2; mi++) {
                uint32_t off = (uint32_t)((wm * 32 + mi * 16 + a_row) * 40 + kk + a_col8) * 2;
                LDSM_X4(ah[mi][0], ah[mi][1], ah[mi][2], ah[mi][3], bs + off);
                LDSM_X4(al[mi][0], al[mi][1], al[mi][2], al[mi][3], bs + OFF_AL + off);
            }
#pragma unroll
            for (int np = 0; np < 4; np++) {
                uint32_t off = (uint32_t)((wn * 64 + np * 16 + b_row) * 40 + kk + b_col8) * 2;
                uint32_t r0, r1, r2, r3;
                LDSM_X4(r0, r1, r2, r3, bs + OFF_BH + off);
                bh[np * 2][0] = r0; bh[np * 2][1] = r1;
                bh[np * 2 + 1][0] = r2; bh[np * 2 + 1][1] = r3;
                LDSM_X4(r0, r1, r2, r3, bs + OFF_BL + off);
                bl[np * 2][0] = r0; bl[np * 2][1] = r1;
                bl[np * 2 + 1][0] = r2; bl[np * 2 + 1][1] = r3;
            }
#pragma unroll
            for (int mi = 0; mi < 2; mi++)
#pragma unroll
                for (int ni = 0; ni < 8; ni++) {
                    MMA16816(d[mi][ni], ah[mi][0], ah[mi][1], ah[mi][2], ah[mi][3],
                             bh[ni][0], bh[ni][1]);
                    MMA16816(d[mi][ni], ah[mi][0], ah[mi][1], ah[mi][2], ah[mi][3],
                             bl[ni][0], bl[ni][1]);
                    MMA16816(d[mi][ni], al[mi][0], al[mi][1], al[mi][2], al[mi][3],
                             bh[ni][0], bh[ni][1]);
                }
        }
        __syncthreads();
    }
#undef STAGE

    const int er = lane >> 2, ec = (lane & 3) * 2;
#pragma unroll
    for (int mi = 0; mi < 2; mi++) {
        float s0 = 0.f, s1 = 0.f, t0 = 0.f, t1 = 0.f;
#pragma unroll
        for (int ni = 0; ni < 8; ni++) {
            int r = row0 + wm * 32 + mi * 16 + er;
            int c = col0 + wn * 64 + ni * 8 + ec;
            float2 v0 = make_float2(d[mi][ni][0], d[mi][ni][1]);
            float2 v1 = make_float2(d[mi][ni][2], d[mi][ni][3]);
            if (BIAS) {
                float b0 = __ldg(&bias[c]), b1 = __ldg(&bias[c + 1]);
                v0.x += b0; v0.y += b1; v1.x += b0; v1.y += b1;
            }
            if (ATTN) {
                int cc = wn * 64 + ni * 8 + ec;
                int head = blockIdx.x;
                float a0 = __ldg(&attS[head * CC + cc]);
                float a1 = __ldg(&attS[head * CC + cc + 1]);
                float e0 = __ldg(&attD[head * CC + cc]);
                float e1 = __ldg(&attD[head * CC + cc + 1]);
                s0 = fmaf(v0.x, a0, fmaf(v0.y, a1, s0));
                s1 = fmaf(v1.x, a0, fmaf(v1.y, a1, s1));
                t0 = fmaf(v0.x, e0, fmaf(v0.y, e1, t0));
                t1 = fmaf(v1.x, e0, fmaf(v1.y, e1, t1));
            }
            *(float2*)&C[(size_t)r * Nn + c] = v0;
            *(float2*)&C[(size_t)(r + 8) * Nn + c] = v1;
        }
        if (ATTN) {
            s0 += __shfl_xor_sync(0xffffffffu, s0, 1);
            s0 += __shfl_xor_sync(0xffffffffu, s0, 2);
            s1 += __shfl_xor_sync(0xffffffffu, s1, 1);
            s1 += __shfl_xor_sync(0xffffffffu, s1, 2);
            t0 += __shfl_xor_sync(0xffffffffu, t0, 1);
            t0 += __shfl_xor_sync(0xffffffffu, t0, 2);
            t1 += __shfl_xor_sync(0xffffffffu, t1, 1);
            t1 += __shfl_xor_sync(0xffffffffu, t1, 2);
            if ((lane & 3) == 0) {
                int head = blockIdx.x;
                int r = row0 + wm * 32 + mi * 16 + er;
                atomicAdd(&g_asrc[r * 4 + head], s0);
                atomicAdd(&g_adst[r * 4 + head], t0);
                atomicAdd(&g_asrc[(r + 8) * 4 + head], s1);
                atomicAdd(&g_adst[(r + 8) * 4 + head], t1);
            }
        }
    }
}

__device__ __forceinline__ float lrelu(float v) { return v > 0.f ? v : NEG * v; }

// ---------------- per-edge weights (lane-parallel, one exp per edge-head) ----
__global__ void __launch_bounds__(256) k_edgew() {
    int lane = threadIdx.x & 31;
    int n = blockIdx.x * 8 + (threadIdx.x >> 5);
    int start = g_rowptr[n], end = g_rowptr[n + 1];
    float4 ad = *(const float4*)&g_adst[n * 4];

    float d0 = 0.f, d1 = 0.f, d2 = 0.f, d3 = 0.f;
    for (int i = start + lane; i < end; i += 32) {
        int s = g_csr[i];
        float4 as = *(const float4*)&g_asrc[s * 4];
        float w0 = __expf(lrelu(as.x + ad.x));
        float w1 = __expf(lrelu(as.y + ad.y));
        float w2 = __expf(lrelu(as.z + ad.z));
        float w3 = __expf(lrelu(as.w + ad.w));
        g_ew[i] = make_float4(w0, w1, w2, w3);
        d0 += w0; d1 += w1; d2 += w2; d3 += w3;
    }
#pragma unroll
    for (int o = 16; o > 0; o >>= 1) {
        d0 += __shfl_xor_sync(0xffffffffu, d0, o);
        d1 += __shfl_xor_sync(0xffffffffu, d1, o);
        d2 += __shfl_xor_sync(0xffffffffu, d2, o);
        d3 += __shfl_xor_sync(0xffffffffu, d3, o);
    }
    if (lane == 0)
        g_dinv[n] = make_float4(1.f / (d0 + 1e-16f), 1.f / (d1 + 1e-16f),
                                1.f / (d2 + 1e-16f), 1.f / (d3 + 1e-16f));
}

// ---------------- aggregation: 2-edge unrolled weighted gather --------------
// warp per node; loads for two edges batched ahead of FMAs (MLP x2).
__global__ void __launch_bounds__(256) k_aggr(const float* __restrict__ h,
                                              const float* __restrict__ bias)
{
    __shared__ float s_sum[CC], s_sq[CC];
    int tid = threadIdx.x;
    if (tid < CC) { s_sum[tid] = 0.f; s_sq[tid] = 0.f; }
    __syncthreads();

    int lane = tid & 31;
    int n = blockIdx.x * 8 + (tid >> 5);
    int start = g_rowptr[n], end = g_rowptr[n + 1];

    const float4* hp = (const float4*)h;
    float4 a0 = make_float4(0.f, 0.f, 0.f, 0.f), a1 = a0, a2 = a0, a3 = a0;

    int i = start;
    for (; i + 2 <= end; i += 2) {
        // batch all loads for two edges (independent -> high MLP)
        int sA = g_csr[i];
        int sB = g_csr[i + 1];
        float4 wA = g_ew[i];
        float4 wB = g_ew[i + 1];
        size_t bA = (size_t)sA * 128;
        size_t bB = (size_t)sB * 128;
        float4 vA0 = hp[bA + lane];
        float4 vA1 = hp[bA + 32 + lane];
        float4 vA2 = hp[bA + 64 + lane];
        float4 vA3 = hp[bA + 96 + lane];
        float4 vB0 = hp[bB + lane];
        float4 vB1 = hp[bB + 32 + lane];
        float4 vB2 = hp[bB + 64 + lane];
        float4 vB3 = hp[bB + 96 + lane];

        a0.x = fmaf(vA0.x, wA.x, a0.x); a0.y = fmaf(vA0.y, wA.x, a0.y);
        a0.z = fmaf(vA0.z, wA.x, a0.z); a0.w = fmaf(vA0.w, wA.x, a0.w);
        a1.x = fmaf(vA1.x, wA.y, a1.x); a1.y = fmaf(vA1.y, wA.y, a1.y);
        a1.z = fmaf(vA1.z, wA.y, a1.z); a1.w = fmaf(vA1.w, wA.y, a1.w);
        a2.x = fmaf(vA2.x, wA.z, a2.x); a2.y = fmaf(vA2.y, wA.z, a2.y);
        a2.z = fmaf(vA2.z, wA.z, a2.z); a2.w = fmaf(vA2.w, wA.z, a2.w);
        a3.x = fmaf(vA3.x, wA.w, a3.x); a3.y = fmaf(vA3.y, wA.w, a3.y);
        a3.z = fmaf(vA3.z, wA.w, a3.z); a3.w = fmaf(vA3.w, wA.w, a3.w);

        a0.x = fmaf(vB0.x, wB.x, a0.x); a0.y = fmaf(vB0.y, wB.x, a0.y);
        a0.z = fmaf(vB0.z, wB.x, a0.z); a0.w = fmaf(vB0.w, wB.x, a0.w);
        a1.x = fmaf(vB1.x, wB.y, a1.x); a1.y = fmaf(vB1.y, wB.y, a1.y);
        a1.z = fmaf(vB1.z, wB.y, a1.z); a1.w = fmaf(vB1.w, wB.y, a1.w);
        a2.x = fmaf(vB2.x, wB.z, a2.x); a2.y = fmaf(vB2.y, wB.z, a2.y);
        a2.z = fmaf(vB2.z, wB.z, a2.z); a2.w = fmaf(vB2.w, wB.z, a2.w);
        a3.x = fmaf(vB3.x, wB.w, a3.x); a3.y = fmaf(vB3.y, wB.w, a3.y);
        a3.z = fmaf(vB3.z, wB.w, a3.z); a3.w = fmaf(vB3.w, wB.w, a3.w);
    }
    if (i < end) {
        int s = g_csr[i];
        float4 w = g_ew[i];
        size_t base = (size_t)s * 128;
        float4 v;
        v = hp[base + lane];
        a0.x = fmaf(v.x, w.x, a0.x); a0.y = fmaf(v.y, w.x, a0.y);
        a0.z = fmaf(v.z, w.x, a0.z); a0.w = fmaf(v.w, w.x, a0.w);
        v = hp[base + 32 + lane];
        a1.x = fmaf(v.x, w.y, a1.x); a1.y = fmaf(v.y, w.y, a1.y);
        a1.z = fmaf(v.z, w.y, a1.z); a1.w = fmaf(v.w, w.y, a1.w);
        v = hp[base + 64 + lane];
        a2.x = fmaf(v.x, w.z, a2.x); a2.y = fmaf(v.y, w.z, a2.y);
        a2.z = fmaf(v.z, w.z, a2.z); a2.w = fmaf(v.w, w.z, a2.w);
        v = hp[base + 96 + lane];
        a3.x = fmaf(v.x, w.w, a3.x); a3.y = fmaf(v.y, w.w, a3.y);
        a3.z = fmaf(v.z, w.w, a3.z); a3.w = fmaf(v.w, w.w, a3.w);
    }
    float4 inv = g_dinv[n];

    float4 bb = ((const float4*)bias)[lane];
    float4 o;
    o.x = 0.25f * (a0.x * inv.x + a1.x * inv.y + a2.x * inv.z + a3.x * inv.w) + bb.x;
    o.y = 0.25f * (a0.y * inv.x + a1.y * inv.y + a2.y * inv.z + a3.y * inv.w) + bb.y;
    o.z = 0.25f * (a0.z * inv.x + a1.z * inv.y + a2.z * inv.z + a3.z * inv.w) + bb.z;
    o.w = 0.25f * (a0.w * inv.x + a1.w * inv.y + a2.w * inv.z + a3.w * inv.w) + bb.w;
    ((float4*)g_t)[(size_t)n * 32 + lane] = o;

    int c = lane * 4;
    atomicAdd(&s_sum[c + 0], o.x); atomicAdd(&s_sq[c + 0], o.x * o.x);
    atomicAdd(&s_sum[c + 1], o.y); atomicAdd(&s_sq[c + 1], o.y * o.y);
    atomicAdd(&s_sum[c + 2], o.z); atomicAdd(&s_sq[c + 2], o.z * o.z);
    atomicAdd(&s_sum[c + 3], o.w); atomicAdd(&s_sq[c + 3], o.w * o.w);
    __syncthreads();
    if (tid < CC) {
        atomicAdd(&g_bnsum[tid], s_sum[tid]);
        atomicAdd(&g_bnsq[tid], s_sq[tid]);
    }
}

__global__ void k_bnfin(const float* __restrict__ g, const float* __restrict__ be) {
    int c = threadIdx.x;
    float mu = g_bnsum[c] * (1.f / NN);
    float var = g_bnsq[c] * (1.f / NN) - mu * mu;
    float sc = g[c] * rsqrtf(var + 1e-5f);
    g_scale[c] = sc;
    g_shift[c] = be[c] - mu * sc;
    g_bnsum[c] = 0.f;
    g_bnsq[c] = 0.f;
}

// ---------------- launch ----------------
extern "C" void kernel_launch(void* const* d_in, const int* in_sizes, int n_in,
                              void* d_out, int out_size)
{
    const float* x   = (const float*)d_in[0];
    const void*  ei  = d_in[1];
    const float* W1  = (const float*)d_in[2];
    const float* as1 = (const float*)d_in[3];
    const float* ad1 = (const float*)d_in[4];
    const float* b1  = (const float*)d_in[5];
    const float* g1  = (const float*)d_in[6];
    const float* be1 = (const float*)d_in[7];
    const float* W2  = (const float*)d_in[8];
    const float* as2 = (const float*)d_in[9];
    const float* ad2 = (const float*)d_in[10];
    const float* b2  = (const float*)d_in[11];
    const float* g2  = (const float*)d_in[12];
    const float* be2 = (const float*)d_in[13];
    const float* Wf  = (const float*)d_in[14];
    const float* bf  = (const float*)d_in[15];
    int E = in_sizes[1] / 2;

    float *ph = nullptr, *pt = nullptr;
    cudaGetSymbolAddress((void**)&ph, g_h);
    cudaGetSymbolAddress((void**)&pt, g_t);
    float* out = (float*)d_out;

    constexpr int SMEM = 81920;
    cudaFuncSetAttribute(k_gemm_m<256, true, false>,
                         cudaFuncAttributeMaxDynamicSharedMemorySize, SMEM);
    cudaFuncSetAttribute(k_gemm_m<128, true, false>,
                         cudaFuncAttributeMaxDynamicSharedMemorySize, SMEM);
    cudaFuncSetAttribute(k_gemm_m<128, false, true>,
                         cudaFuncAttributeMaxDynamicSharedMemorySize, SMEM);

    // layer-1 GEMM chain
    k_prep<<<dim3(HC / 32, FIN / 32), dim3(32, 8)>>>(W1, FIN, HC);
    k_conv<false><<<NN * FIN / 1024, 256>>>((const float4*)x, FIN / 4 - 1);
    k_gemm_m<256, true, false><<<dim3(4, 256), 256, SMEM>>>(ph, HC, as1, ad1, nullptr);

    // CSR build
    k_initdet<<<NN / 256, 256>>>((const unsigned int*)ei);
    k_hist<<<(E + 255) / 256, 256>>>(ei, E);
    k_scan1<<<128, 256>>>();
    k_scan2<<<1, 128>>>();
    k_scan3<<<128, 256>>>();
    k_scatter<<<(E + NN + 255) / 256, 256>>>(ei, E);

    k_edgew<<<4096, 256>>>();
    k_aggr<<<4096, 256>>>(ph, b1);
    k_bnfin<<<1, 128>>>(g1, be1);

    // layer 2
    k_prep<<<dim3(HC / 32, CC / 32), dim3(32, 8)>>>(W2, CC, HC);
    k_conv<true><<<NN * CC / 1024, 256>>>((const float4*)pt, CC / 4 - 1);
    k_gemm_m<128, true, false><<<dim3(4, 256), 256, SMEM>>>(ph, HC, as2, ad2, nullptr);
    k_edgew<<<4096, 256>>>();
    k_aggr<<<4096, 256>>>(ph, b2);
    k_bnfin<<<1, 128>>>(g2, be2);

    // final linear (fp32 out)
    k_prep<<<dim3(CC / 32, CC / 32), dim3(32, 8)>>>(Wf, CC, CC);
    k_conv<true><<<NN * CC / 1024, 256>>>((const float4*)pt, CC / 4 - 1);
    k_gemm_m<128, false, true><<<dim3(1, 256), 256, SMEM>>>(out, CC, nullptr, nullptr, bf);
}

// round 13
// speedup vs baseline: 1.1312x; 1.1252x over previous
#include <cuda_runtime.h>
#include <cuda_bf16.h>
#include <cuda_fp16.h>
#include <cstdint>

#define NN    32768
#define FIN   256
#define HH    4
#define CC    128
#define HC    512
#define EMAX  524288
#define NEG   0.2f

// ---------------- scratch ----------------
__device__ __half g_hh[(size_t)NN * HC];   // post-GEMM features fp16 (gather src)
__device__ float g_t[(size_t)NN * CC];
__device__ float g_asrc[NN * HH];
__device__ float g_adst[NN * HH];
__device__ float4 g_ew[EMAX + NN];         // per-edge unnormalized weights
__device__ float4 g_dinv[NN];              // per-node inverse denominators
__device__ int   g_deg[NN];
__device__ int   g_rowptr[NN + 1];
__device__ int   g_cursor[NN];
__device__ int   g_csr[EMAX + NN];
__device__ float g_bnsum[CC];
__device__ float g_bnsq[CC];
__device__ float g_scale[CC];
__device__ float g_shift[CC];
__device__ int   g_is64;
__device__ int   g_bsum[128];
__device__ __nv_bfloat16 g_Bhi[HC * FIN];
__device__ __nv_bfloat16 g_Blo[HC * FIN];
__device__ __nv_bfloat16 g_Ahi[(size_t)NN * FIN];
__device__ __nv_bfloat16 g_Alo[(size_t)NN * FIN];

__device__ __forceinline__ uint32_t smem_u32(const void* p) {
    uint32_t a;
    asm("{ .reg .u64 t; cvta.to.shared.u64 t, %1; cvt.u32.u64 %0, t; }" : "=r"(a) : "l"(p));
    return a;
}
#define LDSM_X4(r0, r1, r2, r3, addr) \
    asm volatile("ldmatrix.sync.aligned.m8n8.x4.shared.b16 {%0,%1,%2,%3}, [%4];" \
        : "=r"(r0), "=r"(r1), "=r"(r2), "=r"(r3) : "r"(addr))
#define MMA16816(d, a0, a1, a2, a3, b0, b1) \
    asm volatile("mma.sync.aligned.m16n8k16.row.col.f32.bf16.bf16.f32 " \
        "{%0,%1,%2,%3},{%4,%5,%6,%7},{%8,%9},{%0,%1,%2,%3};" \
        : "+f"((d)[0]), "+f"((d)[1]), "+f"((d)[2]), "+f"((d)[3]) \
        : "r"(a0), "r"(a1), "r"(a2), "r"(a3), "r"(b0), "r"(b1))
__device__ __forceinline__ void cp16(uint32_t dst, const void* src) {
    asm volatile("cp.async.cg.shared.global [%0], [%1], 16;" :: "r"(dst), "l"(src));
}
#define CP_COMMIT() asm volatile("cp.async.commit_group;" ::: "memory")

__device__ __forceinline__ int edge_at(const void* ei, int is64, size_t idx) {
    return is64 ? (int)((const long long*)ei)[idx] : ((const int*)ei)[idx];
}

// fp16 pair accumulate: acc += convert(u) * w   (inline fn -> no macro hygiene issues)
__device__ __forceinline__ void acc_h4(float4& acc, uint2 u, float wt) {
    float2 f0 = __half22float2(*(const __half2*)&u.x);
    float2 f1 = __half22float2(*(const __half2*)&u.y);
    acc.x = fmaf(f0.x, wt, acc.x);
    acc.y = fmaf(f0.y, wt, acc.y);
    acc.z = fmaf(f1.x, wt, acc.z);
    acc.w = fmaf(f1.y, wt, acc.w);
}

// ---------------- init + dtype detection (merged) ----------------
__global__ void k_initdet(const unsigned int* __restrict__ ei32) {
    __shared__ unsigned int s_or[256];
    int i = blockIdx.x * blockDim.x + threadIdx.x;
    if (i < NN) g_deg[i] = 1;
    if (i < CC) { g_bnsum[i] = 0.f; g_bnsq[i] = 0.f; }
    if (blockIdx.x == 0) {
        unsigned int v = 0;
        int t = threadIdx.x;
#pragma unroll
        for (int k = 0; k < 8; k++) v |= ei32[2 * (t * 8 + k) + 1];
        s_or[t] = v;
        __syncthreads();
        for (int o = 128; o > 0; o >>= 1) {
            if (t < o) s_or[t] |= s_or[t + o];
            __syncthreads();
        }
        if (t == 0) g_is64 = (s_or[0] == 0) ? 1 : 0;
    }
}

// ---------------- CSR build ----------------
__global__ void k_hist(const void* __restrict__ ei, int E) {
    int e = blockIdx.x * blockDim.x + threadIdx.x;
    int is64 = g_is64;
    if (e < E) atomicAdd(&g_deg[edge_at(ei, is64, (size_t)E + e)], 1);
}
__global__ void k_scan1() {
    __shared__ int s[256];
    int b = blockIdx.x, t = threadIdx.x;
    s[t] = g_deg[b * 256 + t];
    __syncthreads();
    for (int o = 128; o > 0; o >>= 1) {
        if (t < o) s[t] += s[t + o];
        __syncthreads();
    }
    if (t == 0) g_bsum[b] = s[0];
}
__global__ void k_scan2() {
    __shared__ int s[128];
    int t = threadIdx.x;
    int v = g_bsum[t];
    s[t] = v;
    __syncthreads();
    for (int off = 1; off < 128; off <<= 1) {
        int x = (t >= off) ? s[t - off] : 0;
        __syncthreads();
        s[t] += x;
        __syncthreads();
    }
    g_bsum[t] = s[t] - v;
    if (t == 127) g_rowptr[NN] = s[127];
}
__global__ void k_scan3() {
    __shared__ int s[256];
    int b = blockIdx.x, t = threadIdx.x;
    int i = b * 256 + t;
    int v = g_deg[i];
    s[t] = v;
    __syncthreads();
    for (int off = 1; off < 256; off <<= 1) {
        int x = (t >= off) ? s[t - off] : 0;
        __syncthreads();
        s[t] += x;
        __syncthreads();
    }
    int excl = s[t] - v + g_bsum[b];
    g_rowptr[i] = excl;
    g_cursor[i] = excl;
}
__global__ void k_scatter(const void* __restrict__ ei, int E) {
    int e = blockIdx.x * blockDim.x + threadIdx.x;
    int is64 = g_is64;
    if (e < E) {
        int s = edge_at(ei, is64, e);
        int d = edge_at(ei, is64, (size_t)E + e);
        g_csr[atomicAdd(&g_cursor[d], 1)] = s;
    } else if (e < E + NN) {
        int n = e - E;
        g_csr[atomicAdd(&g_cursor[n], 1)] = n;
    }
}

// ---------------- weight pretranspose + split ----------------
__global__ void k_prep(const float* __restrict__ W, int K, int Nn) {
    __shared__ float tile[32][33];
    int nb = blockIdx.x * 32, kb = blockIdx.y * 32;
    for (int j = threadIdx.y; j < 32; j += 8)
        tile[j][threadIdx.x] = W[(size_t)(kb + j) * Nn + nb + threadIdx.x];
    __syncthreads();
    for (int j = threadIdx.y; j < 32; j += 8) {
        float v = tile[threadIdx.x][j];
        __nv_bfloat16 hi = __float2bfloat16_rn(v);
        __nv_bfloat16 lo = __float2bfloat16_rn(v - __bfloat162float(hi));
        size_t o = (size_t)(nb + j) * K + kb + threadIdx.x;
        g_Bhi[o] = hi;
        g_Blo[o] = lo;
    }
}

// ---------------- activation conversion (BN+ReLU fused) -> bf16 hi/lo --------
template <bool FUSE>
__global__ void k_conv(const float4* __restrict__ src, int kmask4) {
    int i = blockIdx.x * blockDim.x + threadIdx.x;
    if (i < NN * HH) { g_asrc[i] = 0.f; g_adst[i] = 0.f; }
    float4 v = src[i];
    if (FUSE) {
        int ch = (i & kmask4) * 4;
        v.x = fmaxf(fmaf(v.x, g_scale[ch + 0], g_shift[ch + 0]), 0.f);
        v.y = fmaxf(fmaf(v.y, g_scale[ch + 1], g_shift[ch + 1]), 0.f);
        v.z = fmaxf(fmaf(v.z, g_scale[ch + 2], g_shift[ch + 2]), 0.f);
        v.w = fmaxf(fmaf(v.w, g_scale[ch + 3], g_shift[ch + 3]), 0.f);
    }
    __nv_bfloat162 h0 = __floats2bfloat162_rn(v.x, v.y);
    __nv_bfloat162 h1 = __floats2bfloat162_rn(v.z, v.w);
    __nv_bfloat162 l0 = __floats2bfloat162_rn(v.x - __bfloat162float(h0.x),
                                              v.y - __bfloat162float(h0.y));
    __nv_bfloat162 l1 = __floats2bfloat162_rn(v.z - __bfloat162float(h1.x),
                                              v.w - __bfloat162float(h1.y));
    *(uint2*)&g_Ahi[(size_t)i * 4] = make_uint2(*(uint32_t*)&h0, *(uint32_t*)&h1);
    *(uint2*)&g_Alo[(size_t)i * 4] = make_uint2(*(uint32_t*)&l0, *(uint32_t*)&l1);
}

// ---------------- cp.async double-buffered bf16 mma GEMM ----------------
// OUTF32=false: h written fp16 to g_hh (+ fused attention dots).
// OUTF32=true : fp32 C with bias (final linear).
template <int K, bool ATTN, bool OUTF32>
__global__ void __launch_bounds__(256) k_gemm_m(
    float* __restrict__ C, int Nn,
    const float* __restrict__ attS, const float* __restrict__ attD,
    const float* __restrict__ bias)
{
    constexpr int NC = K / 32;
    constexpr uint32_t STG = 40960;
    constexpr uint32_t OFF_AL = 10240, OFF_BH = 20480, OFF_BL = 30720;
    extern __shared__ __align__(16) char smraw[];
    const uint32_t sb = smem_u32(smraw);

    const int tid = threadIdx.x;
    const int lane = tid & 31;
    const int wid = tid >> 5;
    const int wm = wid & 3, wn = wid >> 2;
    const int row0 = blockIdx.y * 128, col0 = blockIdx.x * 128;

    float d[2][8][4];
#pragma unroll
    for (int i = 0; i < 2; i++)
#pragma unroll
        for (int j = 0; j < 8; j++)
#pragma unroll
            for (int q = 0; q < 4; q++) d[i][j][q] = 0.f;

    const int c0 = tid, c1 = tid + 256;
    const int r0s = c0 >> 2, kb0 = c0 & 3;
    const int r1s = c1 >> 2, kb1 = c1 & 3;

#define STAGE(kc, s) do { \
    uint32_t b = sb + (s) * STG; \
    cp16(b + r0s * 80 + kb0 * 16, &g_Ahi[(size_t)(row0 + r0s) * K + (kc) * 32 + kb0 * 8]); \
    cp16(b + r1s * 80 + kb1 * 16, &g_Ahi[(size_t)(row0 + r1s) * K + (kc) * 32 + kb1 * 8]); \
    cp16(b + OFF_AL + r0s * 80 + kb0 * 16, &g_Alo[(size_t)(row0 + r0s) * K + (kc) * 32 + kb0 * 8]); \
    cp16(b + OFF_AL + r1s * 80 + kb1 * 16, &g_Alo[(size_t)(row0 + r1s) * K + (kc) * 32 + kb1 * 8]); \
    cp16(b + OFF_BH + r0s * 80 + kb0 * 16, &g_Bhi[(size_t)(col0 + r0s) * K + (kc) * 32 + kb0 * 8]); \
    cp16(b + OFF_BH + r1s * 80 + kb1 * 16, &g_Bhi[(size_t)(col0 + r1s) * K + (kc) * 32 + kb1 * 8]); \
    cp16(b + OFF_BL + r0s * 80 + kb0 * 16, &g_Blo[(size_t)(col0 + r0s) * K + (kc) * 32 + kb0 * 8]); \
    cp16(b + OFF_BL + r1s * 80 + kb1 * 16, &g_Blo[(size_t)(col0 + r1s) * K + (kc) * 32 + kb1 * 8]); \
} while (0)

    STAGE(0, 0);
    CP_COMMIT();

    const int a_row = lane & 15, a_col8 = (lane >> 4) * 8;
    const int b_row = ((lane >> 4) << 3) + (lane & 7), b_col8 = ((lane >> 3) & 1) * 8;

    for (int kc = 0; kc < NC; ++kc) {
        if (kc + 1 < NC) {
            STAGE(kc + 1, (kc + 1) & 1);
            CP_COMMIT();
            asm volatile("cp.async.wait_group 1;" ::: "memory");
        } else {
            asm volatile("cp.async.wait_group 0;" ::: "memory");
        }
        __syncthreads();

        const uint32_t bs = sb + (kc & 1) * STG;
#pragma unroll
        for (int kk = 0; kk < 32; kk += 16) {
            uint32_t ah[2][4], al[2][4], bh[8][2], bl[8][2];
#pragma unroll
            for (int mi = 0; mi < 2; mi++) {
                uint32_t off = (uint32_t)((wm * 32 + mi * 16 + a_row) * 40 + kk + a_col8) * 2;
                LDSM_X4(ah[mi][0], ah[mi][1], ah[mi][2], ah[mi][3], bs + off);
                LDSM_X4(al[mi][0], al[mi][1], al[mi][2], al[mi][3], bs + OFF_AL + off);
            }
#pragma unroll
            for (int np = 0; np < 4; np++) {
                uint32_t off = (uint32_t)((wn * 64 + np * 16 + b_row) * 40 + kk + b_col8) * 2;
                uint32_t r0, r1, r2, r3;
                LDSM_X4(r0, r1, r2, r3, bs + OFF_BH + off);
                bh[np * 2][0] = r0; bh[np * 2][1] = r1;
                bh[np * 2 + 1][0] = r2; bh[np * 2 + 1][1] = r3;
                LDSM_X4(r0, r1, r2, r3, bs + OFF_BL + off);
                bl[np * 2][0] = r0; bl[np * 2][1] = r1;
                bl[np * 2 + 1][0] = r2; bl[np * 2 + 1][1] = r3;
            }
#pragma unroll
            for (int mi = 0; mi < 2; mi++)
#pragma unroll
                for (int ni = 0; ni < 8; ni++) {
                    MMA16816(d[mi][ni], ah[mi][0], ah[mi][1], ah[mi][2], ah[mi][3],
                             bh[ni][0], bh[ni][1]);
                    MMA16816(d[mi][ni], ah[mi][0], ah[mi][1], ah[mi][2], ah[mi][3],
                             bl[ni][0], bl[ni][1]);
                    MMA16816(d[mi][ni], al[mi][0], al[mi][1], al[mi][2], al[mi][3],
                             bh[ni][0], bh[ni][1]);
                }
        }
        __syncthreads();
    }
#undef STAGE

    const int er = lane >> 2, ec = (lane & 3) * 2;
#pragma unroll
    for (int mi = 0; mi < 2; mi++) {
        float s0 = 0.f, s1 = 0.f, t0 = 0.f, t1 = 0.f;
#pragma unroll
        for (int ni = 0; ni < 8; ni++) {
            int r = row0 + wm * 32 + mi * 16 + er;
            int c = col0 + wn * 64 + ni * 8 + ec;
            float2 v0 = make_float2(d[mi][ni][0], d[mi][ni][1]);
            float2 v1 = make_float2(d[mi][ni][2], d[mi][ni][3]);
            if (OUTF32) {
                float b0 = __ldg(&bias[c]), b1 = __ldg(&bias[c + 1]);
                v0.x += b0; v0.y += b1; v1.x += b0; v1.y += b1;
                *(float2*)&C[(size_t)r * Nn + c] = v0;
                *(float2*)&C[(size_t)(r + 8) * Nn + c] = v1;
            } else {
                if (ATTN) {
                    int cc = wn * 64 + ni * 8 + ec;
                    int head = blockIdx.x;
                    float a0 = __ldg(&attS[head * CC + cc]);
                    float a1 = __ldg(&attS[head * CC + cc + 1]);
                    float e0 = __ldg(&attD[head * CC + cc]);
                    float e1 = __ldg(&attD[head * CC + cc + 1]);
                    s0 = fmaf(v0.x, a0, fmaf(v0.y, a1, s0));
                    s1 = fmaf(v1.x, a0, fmaf(v1.y, a1, s1));
                    t0 = fmaf(v0.x, e0, fmaf(v0.y, e1, t0));
                    t1 = fmaf(v1.x, e0, fmaf(v1.y, e1, t1));
                }
                *(__half2*)&g_hh[(size_t)r * Nn + c] = __floats2half2_rn(v0.x, v0.y);
                *(__half2*)&g_hh[(size_t)(r + 8) * Nn + c] = __floats2half2_rn(v1.x, v1.y);
            }
        }
        if (ATTN && !OUTF32) {
            s0 += __shfl_xor_sync(0xffffffffu, s0, 1);
            s0 += __shfl_xor_sync(0xffffffffu, s0, 2);
            s1 += __shfl_xor_sync(0xffffffffu, s1, 1);
            s1 += __shfl_xor_sync(0xffffffffu, s1, 2);
            t0 += __shfl_xor_sync(0xffffffffu, t0, 1);
            t0 += __shfl_xor_sync(0xffffffffu, t0, 2);
            t1 += __shfl_xor_sync(0xffffffffu, t1, 1);
            t1 += __shfl_xor_sync(0xffffffffu, t1, 2);
            if ((lane & 3) == 0) {
                int head = blockIdx.x;
                int r = row0 + wm * 32 + mi * 16 + er;
                atomicAdd(&g_asrc[r * 4 + head], s0);
                atomicAdd(&g_adst[r * 4 + head], t0);
                atomicAdd(&g_asrc[(r + 8) * 4 + head], s1);
                atomicAdd(&g_adst[(r + 8) * 4 + head], t1);
            }
        }
    }
}

__device__ __forceinline__ float lrelu(float v) { return v > 0.f ? v : NEG * v; }

// ---------------- per-edge weights (lane-parallel, one exp per edge-head) ----
__global__ void __launch_bounds__(256) k_edgew() {
    int lane = threadIdx.x & 31;
    int n = blockIdx.x * 8 + (threadIdx.x >> 5);
    int start = g_rowptr[n], end = g_rowptr[n + 1];
    float4 ad = *(const float4*)&g_adst[n * 4];

    float d0 = 0.f, d1 = 0.f, d2 = 0.f, d3 = 0.f;
    for (int i = start + lane; i < end; i += 32) {
        int s = g_csr[i];
        float4 as = *(const float4*)&g_asrc[s * 4];
        float w0 = __expf(lrelu(as.x + ad.x));
        float w1 = __expf(lrelu(as.y + ad.y));
        float w2 = __expf(lrelu(as.z + ad.z));
        float w3 = __expf(lrelu(as.w + ad.w));
        g_ew[i] = make_float4(w0, w1, w2, w3);
        d0 += w0; d1 += w1; d2 += w2; d3 += w3;
    }
#pragma unroll
    for (int o = 16; o > 0; o >>= 1) {
        d0 += __shfl_xor_sync(0xffffffffu, d0, o);
        d1 += __shfl_xor_sync(0xffffffffu, d1, o);
        d2 += __shfl_xor_sync(0xffffffffu, d2, o);
        d3 += __shfl_xor_sync(0xffffffffu, d3, o);
    }
    if (lane == 0)
        g_dinv[n] = make_float4(1.f / (d0 + 1e-16f), 1.f / (d1 + 1e-16f),
                                1.f / (d2 + 1e-16f), 1.f / (d3 + 1e-16f));
}

// ---------------- aggregation: fp16 gather, 2-edge unrolled ----------------
// warp per node; lean exp-free loop; two edges' loads batched (MLP x2);
// fp16 rows halve L2 bytes (1KB/edge vs 2KB).
__global__ void __launch_bounds__(256) k_aggr(const __half* __restrict__ h,
                                              const float* __restrict__ bias)
{
    __shared__ float s_sum[CC], s_sq[CC];
    int tid = threadIdx.x;
    if (tid < CC) { s_sum[tid] = 0.f; s_sq[tid] = 0.f; }
    __syncthreads();

    int lane = tid & 31;
    int n = blockIdx.x * 8 + (tid >> 5);
    int start = g_rowptr[n], end = g_rowptr[n + 1];

    const uint2* hp = (const uint2*)h;    // 4 halves per uint2; row = 128 uint2
    float4 a0 = make_float4(0.f, 0.f, 0.f, 0.f), a1 = a0, a2 = a0, a3 = a0;

    int i = start;
    for (; i + 2 <= end; i += 2) {
        int sA = g_csr[i];
        int sB = g_csr[i + 1];
        float4 wA = g_ew[i];
        float4 wB = g_ew[i + 1];
        size_t bA = (size_t)sA * 128;
        size_t bB = (size_t)sB * 128;
        uint2 uA0 = hp[bA + lane];
        uint2 uA1 = hp[bA + 32 + lane];
        uint2 uA2 = hp[bA + 64 + lane];
        uint2 uA3 = hp[bA + 96 + lane];
        uint2 uB0 = hp[bB + lane];
        uint2 uB1 = hp[bB + 32 + lane];
        uint2 uB2 = hp[bB + 64 + lane];
        uint2 uB3 = hp[bB + 96 + lane];
        acc_h4(a0, uA0, wA.x); acc_h4(a1, uA1, wA.y);
        acc_h4(a2, uA2, wA.z); acc_h4(a3, uA3, wA.w);
        acc_h4(a0, uB0, wB.x); acc_h4(a1, uB1, wB.y);
        acc_h4(a2, uB2, wB.z); acc_h4(a3, uB3, wB.w);
    }
    if (i < end) {
        int s = g_csr[i];
        float4 w = g_ew[i];
        size_t base = (size_t)s * 128;
        uint2 u0 = hp[base + lane];
        uint2 u1 = hp[base + 32 + lane];
        uint2 u2 = hp[base + 64 + lane];
        uint2 u3 = hp[base + 96 + lane];
        acc_h4(a0, u0, w.x); acc_h4(a1, u1, w.y);
        acc_h4(a2, u2, w.z); acc_h4(a3, u3, w.w);
    }
    float4 inv = g_dinv[n];

    float4 bb = ((const float4*)bias)[lane];
    float4 o;
    o.x = 0.25f * (a0.x * inv.x + a1.x * inv.y + a2.x * inv.z + a3.x * inv.w) + bb.x;
    o.y = 0.25f * (a0.y * inv.x + a1.y * inv.y + a2.y * inv.z + a3.y * inv.w) + bb.y;
    o.z = 0.25f * (a0.z * inv.x + a1.z * inv.y + a2.z * inv.z + a3.z * inv.w) + bb.z;
    o.w = 0.25f * (a0.w * inv.x + a1.w * inv.y + a2.w * inv.z + a3.w * inv.w) + bb.w;
    ((float4*)g_t)[(size_t)n * 32 + lane] = o;

    int c = lane * 4;
    atomicAdd(&s_sum[c + 0], o.x); atomicAdd(&s_sq[c + 0], o.x * o.x);
    atomicAdd(&s_sum[c + 1], o.y); atomicAdd(&s_sq[c + 1], o.y * o.y);
    atomicAdd(&s_sum[c + 2], o.z); atomicAdd(&s_sq[c + 2], o.z * o.z);
    atomicAdd(&s_sum[c + 3], o.w); atomicAdd(&s_sq[c + 3], o.w * o.w);
    __syncthreads();
    if (tid < CC) {
        atomicAdd(&g_bnsum[tid], s_sum[tid]);
        atomicAdd(&g_bnsq[tid], s_sq[tid]);
    }
}

__global__ void k_bnfin(const float* __restrict__ g, const float* __restrict__ be) {
    int c = threadIdx.x;
    float mu = g_bnsum[c] * (1.f / NN);
    float var = g_bnsq[c] * (1.f / NN) - mu * mu;
    float sc = g[c] * rsqrtf(var + 1e-5f);
    g_scale[c] = sc;
    g_shift[c] = be[c] - mu * sc;
    g_bnsum[c] = 0.f;
    g_bnsq[c] = 0.f;
}

// ---------------- launch ----------------
extern "C" void kernel_launch(void* const* d_in, const int* in_sizes, int n_in,
                              void* d_out, int out_size)
{
    const float* x   = (const float*)d_in[0];
    const void*  ei  = d_in[1];
    const float* W1  = (const float*)d_in[2];
    const float* as1 = (const float*)d_in[3];
    const float* ad1 = (const float*)d_in[4];
    const float* b1  = (const float*)d_in[5];
    const float* g1  = (const float*)d_in[6];
    const float* be1 = (const float*)d_in[7];
    const float* W2  = (const float*)d_in[8];
    const float* as2 = (const float*)d_in[9];
    const float* ad2 = (const float*)d_in[10];
    const float* b2  = (const float*)d_in[11];
    const float* g2  = (const float*)d_in[12];
    const float* be2 = (const float*)d_in[13];
    const float* Wf  = (const float*)d_in[14];
    const float* bf  = (const float*)d_in[15];
    int E = in_sizes[1] / 2;

    __half* phh = nullptr;
    float* pt = nullptr;
    cudaGetSymbolAddress((void**)&phh, g_hh);
    cudaGetSymbolAddress((void**)&pt, g_t);
    float* out = (float*)d_out;

    constexpr int SMEM = 81920;
    cudaFuncSetAttribute(k_gemm_m<256, true, false>,
                         cudaFuncAttributeMaxDynamicSharedMemorySize, SMEM);
    cudaFuncSetAttribute(k_gemm_m<128, true, false>,
                         cudaFuncAttributeMaxDynamicSharedMemorySize, SMEM);
    cudaFuncSetAttribute(k_gemm_m<128, false, true>,
                         cudaFuncAttributeMaxDynamicSharedMemorySize, SMEM);

    // layer-1 GEMM chain
    k_prep<<<dim3(HC / 32, FIN / 32), dim3(32, 8)>>>(W1, FIN, HC);
    k_conv<false><<<NN * FIN / 1024, 256>>>((const float4*)x, FIN / 4 - 1);
    k_gemm_m<256, true, false><<<dim3(4, 256), 256, SMEM>>>(nullptr, HC, as1, ad1, nullptr);

    // CSR build
    k_initdet<<<NN / 256, 256>>>((const unsigned int*)ei);
    k_hist<<<(E + 255) / 256, 256>>>(ei, E);
    k_scan1<<<128, 256>>>();
    k_scan2<<<1, 128>>>();
    k_scan3<<<128, 256>>>();
    k_scatter<<<(E + NN + 255) / 256, 256>>>(ei, E);

    k_edgew<<<4096, 256>>>();
    k_aggr<<<4096, 256>>>(phh, b1);
    k_bnfin<<<1, 128>>>(g1, be1);

    // layer 2
    k_prep<<<dim3(HC / 32, CC / 32), dim3(32, 8)>>>(W2, CC, HC);
    k_conv<true><<<NN * CC / 1024, 256>>>((const float4*)pt, CC / 4 - 1);
    k_gemm_m<128, true, false><<<dim3(4, 256), 256, SMEM>>>(nullptr, HC, as2, ad2, nullptr);
    k_edgew<<<4096, 256>>>();
    k_aggr<<<4096, 256>>>(phh, b2);
    k_bnfin<<<1, 128>>>(g2, be2);

    // final linear (fp32 out)
    k_prep<<<dim3(CC / 32, CC / 32), dim3(32, 8)>>>(Wf, CC, CC);
    k_conv<true><<<NN * CC / 1024, 256>>>((const float4*)pt, CC / 4 - 1);
    k_gemm_m<128, false, true><<<dim3(1, 256), 256, SMEM>>>(out, CC, nullptr, nullptr, bf);
}

// round 14
// speedup vs baseline: 1.1663x; 1.0310x over previous
#include <cuda_runtime.h>
#include <cuda_bf16.h>
#include <cuda_fp16.h>
#include <cstdint>

#define NN    32768
#define FIN   256
#define HH    4
#define CC    128
#define HC    512
#define EMAX  524288
#define NEG   0.2f

// ---------------- scratch ----------------
__device__ __half g_hh[(size_t)NN * HC];   // post-GEMM features fp16 (gather src)
__device__ float g_t[(size_t)NN * CC];
__device__ float g_asrc[NN * HH];
__device__ float g_adst[NN * HH];
__device__ float4 g_ew[EMAX + NN];         // per-edge unnormalized weights
__device__ float4 g_dinv[NN];              // per-node inverse denominators
__device__ int   g_deg[NN];
__device__ int   g_rowptr[NN + 1];
__device__ int   g_cursor[NN];
__device__ int   g_csr[EMAX + NN];
__device__ float g_bnsum[CC];
__device__ float g_bnsq[CC];
__device__ float g_scale[CC];
__device__ float g_shift[CC];
__device__ int   g_is64;
__device__ int   g_bsum[128];
__device__ __nv_bfloat16 g_Bhi[HC * FIN];
__device__ __nv_bfloat16 g_Blo[HC * FIN];
__device__ __nv_bfloat16 g_Ahi[(size_t)NN * FIN];
__device__ __nv_bfloat16 g_Alo[(size_t)NN * FIN];

__device__ __forceinline__ uint32_t smem_u32(const void* p) {
    uint32_t a;
    asm("{ .reg .u64 t; cvta.to.shared.u64 t, %1; cvt.u32.u64 %0, t; }" : "=r"(a) : "l"(p));
    return a;
}
#define LDSM_X4(r0, r1, r2, r3, addr) \
    asm volatile("ldmatrix.sync.aligned.m8n8.x4.shared.b16 {%0,%1,%2,%3}, [%4];" \
        : "=r"(r0), "=r"(r1), "=r"(r2), "=r"(r3) : "r"(addr))
#define MMA16816(d, a0, a1, a2, a3, b0, b1) \
    asm volatile("mma.sync.aligned.m16n8k16.row.col.f32.bf16.bf16.f32 " \
        "{%0,%1,%2,%3},{%4,%5,%6,%7},{%8,%9},{%0,%1,%2,%3};" \
        : "+f"((d)[0]), "+f"((d)[1]), "+f"((d)[2]), "+f"((d)[3]) \
        : "r"(a0), "r"(a1), "r"(a2), "r"(a3), "r"(b0), "r"(b1))
__device__ __forceinline__ void cp16(uint32_t dst, const void* src) {
    asm volatile("cp.async.cg.shared.global [%0], [%1], 16;" :: "r"(dst), "l"(src));
}
#define CP_COMMIT() asm volatile("cp.async.commit_group;" ::: "memory")

__device__ __forceinline__ int edge_at(const void* ei, int is64, size_t idx) {
    return is64 ? (int)((const long long*)ei)[idx] : ((const int*)ei)[idx];
}

// fp16 pair accumulate: acc += convert(u) * wt
__device__ __forceinline__ void acc_h4(float4& acc, uint2 u, float wt) {
    float2 f0 = __half22float2(*(const __half2*)&u.x);
    float2 f1 = __half22float2(*(const __half2*)&u.y);
    acc.x = fmaf(f0.x, wt, acc.x);
    acc.y = fmaf(f0.y, wt, acc.y);
    acc.z = fmaf(f1.x, wt, acc.z);
    acc.w = fmaf(f1.y, wt, acc.w);
}

// ---------------- init + dtype detection (merged) ----------------
__global__ void k_initdet(const unsigned int* __restrict__ ei32) {
    __shared__ unsigned int s_or[256];
    int i = blockIdx.x * blockDim.x + threadIdx.x;
    if (i < NN) g_deg[i] = 1;
    if (i < CC) { g_bnsum[i] = 0.f; g_bnsq[i] = 0.f; }
    if (blockIdx.x == 0) {
        unsigned int v = 0;
        int t = threadIdx.x;
#pragma unroll
        for (int k = 0; k < 8; k++) v |= ei32[2 * (t * 8 + k) + 1];
        s_or[t] = v;
        __syncthreads();
        for (int o = 128; o > 0; o >>= 1) {
            if (t < o) s_or[t] |= s_or[t + o];
            __syncthreads();
        }
        if (t == 0) g_is64 = (s_or[0] == 0) ? 1 : 0;
    }
}

// ---------------- CSR build ----------------
__global__ void k_hist(const void* __restrict__ ei, int E) {
    int e = blockIdx.x * blockDim.x + threadIdx.x;
    int is64 = g_is64;
    if (e < E) atomicAdd(&g_deg[edge_at(ei, is64, (size_t)E + e)], 1);
}
__global__ void k_scan1() {
    __shared__ int s[256];
    int b = blockIdx.x, t = threadIdx.x;
    s[t] = g_deg[b * 256 + t];
    __syncthreads();
    for (int o = 128; o > 0; o >>= 1) {
        if (t < o) s[t] += s[t + o];
        __syncthreads();
    }
    if (t == 0) g_bsum[b] = s[0];
}
__global__ void k_scan2() {
    __shared__ int s[128];
    int t = threadIdx.x;
    int v = g_bsum[t];
    s[t] = v;
    __syncthreads();
    for (int off = 1; off < 128; off <<= 1) {
        int x = (t >= off) ? s[t - off] : 0;
        __syncthreads();
        s[t] += x;
        __syncthreads();
    }
    g_bsum[t] = s[t] - v;
    if (t == 127) g_rowptr[NN] = s[127];
}
__global__ void k_scan3() {
    __shared__ int s[256];
    int b = blockIdx.x, t = threadIdx.x;
    int i = b * 256 + t;
    int v = g_deg[i];
    s[t] = v;
    __syncthreads();
    for (int off = 1; off < 256; off <<= 1) {
        int x = (t >= off) ? s[t - off] : 0;
        __syncthreads();
        s[t] += x;
        __syncthreads();
    }
    int excl = s[t] - v + g_bsum[b];
    g_rowptr[i] = excl;
    g_cursor[i] = excl;
}
__global__ void k_scatter(const void* __restrict__ ei, int E) {
    int e = blockIdx.x * blockDim.x + threadIdx.x;
    int is64 = g_is64;
    if (e < E) {
        int s = edge_at(ei, is64, e);
        int d = edge_at(ei, is64, (size_t)E + e);
        g_csr[atomicAdd(&g_cursor[d], 1)] = s;
    } else if (e < E + NN) {
        int n = e - E;
        g_csr[atomicAdd(&g_cursor[n], 1)] = n;
    }
}

// ---------------- weight pretranspose + split ----------------
__global__ void k_prep(const float* __restrict__ W, int K, int Nn) {
    __shared__ float tile[32][33];
    int nb = blockIdx.x * 32, kb = blockIdx.y * 32;
    for (int j = threadIdx.y; j < 32; j += 8)
        tile[j][threadIdx.x] = W[(size_t)(kb + j) * Nn + nb + threadIdx.x];
    __syncthreads();
    for (int j = threadIdx.y; j < 32; j += 8) {
        float v = tile[threadIdx.x][j];
        __nv_bfloat16 hi = __float2bfloat16_rn(v);
        __nv_bfloat16 lo = __float2bfloat16_rn(v - __bfloat162float(hi));
        size_t o = (size_t)(nb + j) * K + kb + threadIdx.x;
        g_Bhi[o] = hi;
        g_Blo[o] = lo;
    }
}

// ---------------- activation conversion (BN+ReLU fused) -> bf16 hi/lo --------
template <bool FUSE>
__global__ void k_conv(const float4* __restrict__ src, int kmask4) {
    int i = blockIdx.x * blockDim.x + threadIdx.x;
    if (i < NN * HH) { g_asrc[i] = 0.f; g_adst[i] = 0.f; }
    float4 v = src[i];
    if (FUSE) {
        int ch = (i & kmask4) * 4;
        v.x = fmaxf(fmaf(v.x, g_scale[ch + 0], g_shift[ch + 0]), 0.f);
        v.y = fmaxf(fmaf(v.y, g_scale[ch + 1], g_shift[ch + 1]), 0.f);
        v.z = fmaxf(fmaf(v.z, g_scale[ch + 2], g_shift[ch + 2]), 0.f);
        v.w = fmaxf(fmaf(v.w, g_scale[ch + 3], g_shift[ch + 3]), 0.f);
    }
    __nv_bfloat162 h0 = __floats2bfloat162_rn(v.x, v.y);
    __nv_bfloat162 h1 = __floats2bfloat162_rn(v.z, v.w);
    __nv_bfloat162 l0 = __floats2bfloat162_rn(v.x - __bfloat162float(h0.x),
                                              v.y - __bfloat162float(h0.y));
    __nv_bfloat162 l1 = __floats2bfloat162_rn(v.z - __bfloat162float(h1.x),
                                              v.w - __bfloat162float(h1.y));
    *(uint2*)&g_Ahi[(size_t)i * 4] = make_uint2(*(uint32_t*)&h0, *(uint32_t*)&h1);
    *(uint2*)&g_Alo[(size_t)i * 4] = make_uint2(*(uint32_t*)&l0, *(uint32_t*)&l1);
}

// ---------------- cp.async double-buffered bf16 mma GEMM ----------------
// OUTF32=false: h written fp16 to g_hh (+ fused attention dots).
// OUTF32=true : fp32 C with bias (final linear).
// min-blocks=2: force 2 CTAs/SM (regs cap 128 = current usage; smem 2x80KB fits)
template <int K, bool ATTN, bool OUTF32>
__global__ void __launch_bounds__(256, 2) k_gemm_m(
    float* __restrict__ C, int Nn,
    const float* __restrict__ attS, const float* __restrict__ attD,
    const float* __restrict__ bias)
{
    constexpr int NC = K / 32;
    constexpr uint32_t STG = 40960;
    constexpr uint32_t OFF_AL = 10240, OFF_BH = 20480, OFF_BL = 30720;
    extern __shared__ __align__(16) char smraw[];
    const uint32_t sb = smem_u32(smraw);

    const int tid = threadIdx.x;
    const int lane = tid & 31;
    const int wid = tid >> 5;
    const int wm = wid & 3, wn = wid >> 2;
    const int row0 = blockIdx.y * 128, col0 = blockIdx.x * 128;

    float d[2][8][4];
#pragma unroll
    for (int i = 0; i < 2; i++)
#pragma unroll
        for (int j = 0; j < 8; j++)
#pragma unroll
            for (int q = 0; q < 4; q++) d[i][j][q] = 0.f;

    const int c0 = tid, c1 = tid + 256;
    const int r0s = c0 >> 2, kb0 = c0 & 3;
    const int r1s = c1 >> 2, kb1 = c1 & 3;

#define STAGE(kc, s) do { \
    uint32_t b = sb + (s) * STG; \
    cp16(b + r0s * 80 + kb0 * 16, &g_Ahi[(size_t)(row0 + r0s) * K + (kc) * 32 + kb0 * 8]); \
    cp16(b + r1s * 80 + kb1 * 16, &g_Ahi[(size_t)(row0 + r1s) * K + (kc) * 32 + kb1 * 8]); \
    cp16(b + OFF_AL + r0s * 80 + kb0 * 16, &g_Alo[(size_t)(row0 + r0s) * K + (kc) * 32 + kb0 * 8]); \
    cp16(b + OFF_AL + r1s * 80 + kb1 * 16, &g_Alo[(size_t)(row0 + r1s) * K + (kc) * 32 + kb1 * 8]); \
    cp16(b + OFF_BH + r0s * 80 + kb0 * 16, &g_Bhi[(size_t)(col0 + r0s) * K + (kc) * 32 + kb0 * 8]); \
    cp16(b + OFF_BH + r1s * 80 + kb1 * 16, &g_Bhi[(size_t)(col0 + r1s) * K + (kc) * 32 + kb1 * 8]); \
    cp16(b + OFF_BL + r0s * 80 + kb0 * 16, &g_Blo[(size_t)(col0 + r0s) * K + (kc) * 32 + kb0 * 8]); \
    cp16(b + OFF_BL + r1s * 80 + kb1 * 16, &g_Blo[(size_t)(col0 + r1s) * K + (kc) * 32 + kb1 * 8]); \
} while (0)

    STAGE(0, 0);
    CP_COMMIT();

    const int a_row = lane & 15, a_col8 = (lane >> 4) * 8;
    const int b_row = ((lane >> 4) << 3) + (lane & 7), b_col8 = ((lane >> 3) & 1) * 8;

    for (int kc = 0; kc < NC; ++kc) {
        if (kc + 1 < NC) {
            STAGE(kc + 1, (kc + 1) & 1);
            CP_COMMIT();
            asm volatile("cp.async.wait_group 1;" ::: "memory");
        } else {
            asm volatile("cp.async.wait_group 0;" ::: "memory");
        }
        __syncthreads();

        const uint32_t bs = sb + (kc & 1) * STG;
#pragma unroll
        for (int kk = 0; kk < 32; kk += 16) {
            uint32_t ah[2][4], al[2][4], bh[8][2], bl[8][2];
#pragma unroll
            for (int mi = 0; mi < 2; mi++) {
                uint32_t off = (uint32_t)((wm * 32 + mi * 16 + a_row) * 40 + kk + a_col8) * 2;
                LDSM_X4(ah[mi][0], ah[mi][1], ah[mi][2], ah[mi][3], bs + off);
                LDSM_X4(al[mi][0], al[mi][1], al[mi][2], al[mi][3], bs + OFF_AL + off);
            }
#pragma unroll
            for (int np = 0; np < 4; np++) {
                uint32_t off = (uint32_t)((wn * 64 + np * 16 + b_row) * 40 + kk + b_col8) * 2;
                uint32_t r0, r1, r2, r3;
                LDSM_X4(r0, r1, r2, r3, bs + OFF_BH + off);
                bh[np * 2][0] = r0; bh[np * 2][1] = r1;
                bh[np * 2 + 1][0] = r2; bh[np * 2 + 1][1] = r3;
                LDSM_X4(r0, r1, r2, r3, bs + OFF_BL + off);
                bl[np * 2][0] = r0; bl[np * 2][1] = r1;
                bl[np * 2 + 1][0] = r2; bl[np * 2 + 1][1] = r3;
            }
#pragma unroll
            for (int mi = 0; mi < 2; mi++)
#pragma unroll
                for (int ni = 0; ni < 8; ni++) {
                    MMA16816(d[mi][ni], ah[mi][0], ah[mi][1], ah[mi][2], ah[mi][3],
                             bh[ni][0], bh[ni][1]);
                    MMA16816(d[mi][ni], ah[mi][0], ah[mi][1], ah[mi][2], ah[mi][3],
                             bl[ni][0], bl[ni][1]);
                    MMA16816(d[mi][ni], al[mi][0], al[mi][1], al[mi][2], al[mi][3],
                             bh[ni][0], bh[ni][1]);
                }
        }
        __syncthreads();
    }
#undef STAGE

    const int er = lane >> 2, ec = (lane & 3) * 2;
#pragma unroll
    for (int mi = 0; mi < 2; mi++) {
        float s0 = 0.f, s1 = 0.f, t0 = 0.f, t1 = 0.f;
#pragma unroll
        for (int ni = 0; ni < 8; ni++) {
            int r = row0 + wm * 32 + mi * 16 + er;
            int c = col0 + wn * 64 + ni * 8 + ec;
            float2 v0 = make_float2(d[mi][ni][0], d[mi][ni][1]);
            float2 v1 = make_float2(d[mi][ni][2], d[mi][ni][3]);
            if (OUTF32) {
                float b0 = __ldg(&bias[c]), b1 = __ldg(&bias[c + 1]);
                v0.x += b0; v0.y += b1; v1.x += b0; v1.y += b1;
                *(float2*)&C[(size_t)r * Nn + c] = v0;
                *(float2*)&C[(size_t)(r + 8) * Nn + c] = v1;
            } else {
                if (ATTN) {
                    int cc = wn * 64 + ni * 8 + ec;
                    int head = blockIdx.x;
                    float a0 = __ldg(&attS[head * CC + cc]);
                    float a1 = __ldg(&attS[head * CC + cc + 1]);
                    float e0 = __ldg(&attD[head * CC + cc]);
                    float e1 = __ldg(&attD[head * CC + cc + 1]);
                    s0 = fmaf(v0.x, a0, fmaf(v0.y, a1, s0));
                    s1 = fmaf(v1.x, a0, fmaf(v1.y, a1, s1));
                    t0 = fmaf(v0.x, e0, fmaf(v0.y, e1, t0));
                    t1 = fmaf(v1.x, e0, fmaf(v1.y, e1, t1));
                }
                *(__half2*)&g_hh[(size_t)r * Nn + c] = __floats2half2_rn(v0.x, v0.y);
                *(__half2*)&g_hh[(size_t)(r + 8) * Nn + c] = __floats2half2_rn(v1.x, v1.y);
            }
        }
        if (ATTN && !OUTF32) {
            s0 += __shfl_xor_sync(0xffffffffu, s0, 1);
            s0 += __shfl_xor_sync(0xffffffffu, s0, 2);
            s1 += __shfl_xor_sync(0xffffffffu, s1, 1);
            s1 += __shfl_xor_sync(0xffffffffu, s1, 2);
            t0 += __shfl_xor_sync(0xffffffffu, t0, 1);
            t0 += __shfl_xor_sync(0xffffffffu, t0, 2);
            t1 += __shfl_xor_sync(0xffffffffu, t1, 1);
            t1 += __shfl_xor_sync(0xffffffffu, t1, 2);
            if ((lane & 3) == 0) {
                int head = blockIdx.x;
                int r = row0 + wm * 32 + mi * 16 + er;
                atomicAdd(&g_asrc[r * 4 + head], s0);
                atomicAdd(&g_adst[r * 4 + head], t0);
                atomicAdd(&g_asrc[(r + 8) * 4 + head], s1);
                atomicAdd(&g_adst[(r + 8) * 4 + head], t1);
            }
        }
    }
}

__device__ __forceinline__ float lrelu(float v) { return v > 0.f ? v : NEG * v; }

// ---------------- per-edge weights (lane-parallel, one exp per edge-head) ----
__global__ void __launch_bounds__(256) k_edgew() {
    int lane = threadIdx.x & 31;
    int n = blockIdx.x * 8 + (threadIdx.x >> 5);
    int start = g_rowptr[n], end = g_rowptr[n + 1];
    float4 ad = *(const float4*)&g_adst[n * 4];

    float d0 = 0.f, d1 = 0.f, d2 = 0.f, d3 = 0.f;
    for (int i = start + lane; i < end; i += 32) {
        int s = g_csr[i];
        float4 as = *(const float4*)&g_asrc[s * 4];
        float w0 = __expf(lrelu(as.x + ad.x));
        float w1 = __expf(lrelu(as.y + ad.y));
        float w2 = __expf(lrelu(as.z + ad.z));
        float w3 = __expf(lrelu(as.w + ad.w));
        g_ew[i] = make_float4(w0, w1, w2, w3);
        d0 += w0; d1 += w1; d2 += w2; d3 += w3;
    }
#pragma unroll
    for (int o = 16; o > 0; o >>= 1) {
        d0 += __shfl_xor_sync(0xffffffffu, d0, o);
        d1 += __shfl_xor_sync(0xffffffffu, d1, o);
        d2 += __shfl_xor_sync(0xffffffffu, d2, o);
        d3 += __shfl_xor_sync(0xffffffffu, d3, o);
    }
    if (lane == 0)
        g_dinv[n] = make_float4(1.f / (d0 + 1e-16f), 1.f / (d1 + 1e-16f),
                                1.f / (d2 + 1e-16f), 1.f / (d3 + 1e-16f));
}

// ---------------- aggregation: fp16 gather, 4-edge batched loads ------------
__global__ void __launch_bounds__(256) k_aggr(const __half* __restrict__ h,
                                              const float* __restrict__ bias)
{
    __shared__ float s_sum[CC], s_sq[CC];
    int tid = threadIdx.x;
    if (tid < CC) { s_sum[tid] = 0.f; s_sq[tid] = 0.f; }
    __syncthreads();

    int lane = tid & 31;
    int n = blockIdx.x * 8 + (tid >> 5);
    int start = g_rowptr[n], end = g_rowptr[n + 1];

    const uint2* hp = (const uint2*)h;    // 4 halves per uint2; row = 128 uint2
    float4 a0 = make_float4(0.f, 0.f, 0.f, 0.f), a1 = a0, a2 = a0, a3 = a0;

    int i = start;
    for (; i + 4 <= end; i += 4) {
        int s0i = g_csr[i], s1i = g_csr[i + 1], s2i = g_csr[i + 2], s3i = g_csr[i + 3];
        float4 w0 = g_ew[i], w1 = g_ew[i + 1], w2 = g_ew[i + 2], w3 = g_ew[i + 3];
        size_t b0 = (size_t)s0i * 128, b1 = (size_t)s1i * 128;
        size_t b2 = (size_t)s2i * 128, b3 = (size_t)s3i * 128;
        uint2 uA0 = hp[b0 + lane],      uA1 = hp[b0 + 32 + lane];
        uint2 uA2 = hp[b0 + 64 + lane], uA3 = hp[b0 + 96 + lane];
        uint2 uB0 = hp[b1 + lane],      uB1 = hp[b1 + 32 + lane];
        uint2 uB2 = hp[b1 + 64 + lane], uB3 = hp[b1 + 96 + lane];
        uint2 uC0 = hp[b2 + lane],      uC1 = hp[b2 + 32 + lane];
        uint2 uC2 = hp[b2 + 64 + lane], uC3 = hp[b2 + 96 + lane];
        uint2 uD0 = hp[b3 + lane],      uD1 = hp[b3 + 32 + lane];
        uint2 uD2 = hp[b3 + 64 + lane], uD3 = hp[b3 + 96 + lane];
        acc_h4(a0, uA0, w0.x); acc_h4(a1, uA1, w0.y); acc_h4(a2, uA2, w0.z); acc_h4(a3, uA3, w0.w);
        acc_h4(a0, uB0, w1.x); acc_h4(a1, uB1, w1.y); acc_h4(a2, uB2, w1.z); acc_h4(a3, uB3, w1.w);
        acc_h4(a0, uC0, w2.x); acc_h4(a1, uC1, w2.y); acc_h4(a2, uC2, w2.z); acc_h4(a3, uC3, w2.w);
        acc_h4(a0, uD0, w3.x); acc_h4(a1, uD1, w3.y); acc_h4(a2, uD2, w3.z); acc_h4(a3, uD3, w3.w);
    }
    for (; i < end; ++i) {
        int s = g_csr[i];
        float4 w = g_ew[i];
        size_t base = (size_t)s * 128;
        uint2 u0 = hp[base + lane];
        uint2 u1 = hp[base + 32 + lane];
        uint2 u2 = hp[base + 64 + lane];
        uint2 u3 = hp[base + 96 + lane];
        acc_h4(a0, u0, w.x); acc_h4(a1, u1, w.y);
        acc_h4(a2, u2, w.z); acc_h4(a3, u3, w.w);
    }
    float4 inv = g_dinv[n];

    float4 bb = ((const float4*)bias)[lane];
    float4 o;
    o.x = 0.25f * (a0.x * inv.x + a1.x * inv.y + a2.x * inv.z + a3.x * inv.w) + bb.x;
    o.y = 0.25f * (a0.y * inv.x + a1.y * inv.y + a2.y * inv.z + a3.y * inv.w) + bb.y;
    o.z = 0.25f * (a0.z * inv.x + a1.z * inv.y + a2.z * inv.z + a3.z * inv.w) + bb.z;
    o.w = 0.25f * (a0.w * inv.x + a1.w * inv.y + a2.w * inv.z + a3.w * inv.w) + bb.w;
    ((float4*)g_t)[(size_t)n * 32 + lane] = o;

    int c = lane * 4;
    atomicAdd(&s_sum[c + 0], o.x); atomicAdd(&s_sq[c + 0], o.x * o.x);
    atomicAdd(&s_sum[c + 1], o.y); atomicAdd(&s_sq[c + 1], o.y * o.y);
    atomicAdd(&s_sum[c + 2], o.z); atomicAdd(&s_sq[c + 2], o.z * o.z);
    atomicAdd(&s_sum[c + 3], o.w); atomicAdd(&s_sq[c + 3], o.w * o.w);
    __syncthreads();
    if (tid < CC) {
        atomicAdd(&g_bnsum[tid], s_sum[tid]);
        atomicAdd(&g_bnsq[tid], s_sq[tid]);
    }
}

__global__ void k_bnfin(const float* __restrict__ g, const float* __restrict__ be) {
    int c = threadIdx.x;
    float mu = g_bnsum[c] * (1.f / NN);
    float var = g_bnsq[c] * (1.f / NN) - mu * mu;
    float sc = g[c] * rsqrtf(var + 1e-5f);
    g_scale[c] = sc;
    g_shift[c] = be[c] - mu * sc;
    g_bnsum[c] = 0.f;
    g_bnsq[c] = 0.f;
}

// ---------------- launch ----------------
extern "C" void kernel_launch(void* const* d_in, const int* in_sizes, int n_in,
                              void* d_out, int out_size)
{
    const float* x   = (const float*)d_in[0];
    const void*  ei  = d_in[1];
    const float* W1  = (const float*)d_in[2];
    const float* as1 = (const float*)d_in[3];
    const float* ad1 = (const float*)d_in[4];
    const float* b1  = (const float*)d_in[5];
    const float* g1  = (const float*)d_in[6];
    const float* be1 = (const float*)d_in[7];
    const float* W2  = (const float*)d_in[8];
    const float* as2 = (const float*)d_in[9];
    const float* ad2 = (const float*)d_in[10];
    const float* b2  = (const float*)d_in[11];
    const float* g2  = (const float*)d_in[12];
    const float* be2 = (const float*)d_in[13];
    const float* Wf  = (const float*)d_in[14];
    const float* bf  = (const float*)d_in[15];
    int E = in_sizes[1] / 2;

    __half* phh = nullptr;
    float* pt = nullptr;
    cudaGetSymbolAddress((void**)&phh, g_hh);
    cudaGetSymbolAddress((void**)&pt, g_t);
    float* out = (float*)d_out;

    constexpr int SMEM = 81920;
    cudaFuncSetAttribute(k_gemm_m<256, true, false>,
                         cudaFuncAttributeMaxDynamicSharedMemorySize, SMEM);
    cudaFuncSetAttribute(k_gemm_m<128, true, false>,
                         cudaFuncAttributeMaxDynamicSharedMemorySize, SMEM);
    cudaFuncSetAttribute(k_gemm_m<128, false, true>,
                         cudaFuncAttributeMaxDynamicSharedMemorySize, SMEM);

    // layer-1 GEMM chain
    k_prep<<<dim3(HC / 32, FIN / 32), dim3(32, 8)>>>(W1, FIN, HC);
    k_conv<false><<<NN * FIN / 1024, 256>>>((const float4*)x, FIN / 4 - 1);
    k_gemm_m<256, true, false><<<dim3(4, 256), 256, SMEM>>>(nullptr, HC, as1, ad1, nullptr);

    // CSR build
    k_initdet<<<NN / 256, 256>>>((const unsigned int*)ei);
    k_hist<<<(E + 255) / 256, 256>>>(ei, E);
    k_scan1<<<128, 256>>>();
    k_scan2<<<1, 128>>>();
    k_scan3<<<128, 256>>>();
    k_scatter<<<(E + NN + 255) / 256, 256>>>(ei, E);

    k_edgew<<<4096, 256>>>();
    k_aggr<<<4096, 256>>>(phh, b1);
    k_bnfin<<<1, 128>>>(g1, be1);

    // layer 2
    k_prep<<<dim3(HC / 32, CC / 32), dim3(32, 8)>>>(W2, CC, HC);
    k_conv<true><<<NN * CC / 1024, 256>>>((const float4*)pt, CC / 4 - 1);
    k_gemm_m<128, true, false><<<dim3(4, 256), 256, SMEM>>>(nullptr, HC, as2, ad2, nullptr);
    k_edgew<<<4096, 256>>>();
    k_aggr<<<4096, 256>>>(phh, b2);
    k_bnfin<<<1, 128>>>(g2, be2);

    // final linear (fp32 out)
    k_prep<<<dim3(CC / 32, CC / 32), dim3(32, 8)>>>(Wf, CC, CC);
    k_conv<true><<<NN * CC / 1024, 256>>>((const float4*)pt, CC / 4 - 1);
    k_gemm_m<128, false, true><<<dim3(1, 256), 256, SMEM>>>(out, CC, nullptr, nullptr, bf);
}

// round 15
// speedup vs baseline: 1.2167x; 1.0432x over previous
#include <cuda_runtime.h>
#include <cuda_bf16.h>
#include <cuda_fp16.h>
#include <cstdint>

#define NN    32768
#define FIN   256
#define HH    4
#define CC    128
#define HC    512
#define EMAX  524288
#define NEG   0.2f

// ---------------- scratch ----------------
__device__ __half g_hh[(size_t)NN * HC];   // post-GEMM features fp16 (gather src)
__device__ float g_t[(size_t)NN * CC];
__device__ float g_asrc[NN * HH];
__device__ float g_adst[NN * HH];
__device__ float4 g_ew[EMAX + NN];         // per-edge unnormalized weights
__device__ float4 g_dinv[NN];              // per-node inverse denominators
__device__ int   g_deg[NN];
__device__ int   g_rowptr[NN + 1];
__device__ int   g_cursor[NN];
__device__ int   g_csr[EMAX + NN];
__device__ float g_bnsum[CC];
__device__ float g_bnsq[CC];
__device__ int   g_is64;
__device__ int   g_scnt;
__device__ int   g_bsum[128];
__device__ __nv_bfloat16 g_Bhi[HC * FIN];
__device__ __nv_bfloat16 g_Blo[HC * FIN];
__device__ __nv_bfloat16 g_Ahi[(size_t)NN * FIN];
__device__ __nv_bfloat16 g_Alo[(size_t)NN * FIN];

__device__ __forceinline__ uint32_t smem_u32(const void* p) {
    uint32_t a;
    asm("{ .reg .u64 t; cvta.to.shared.u64 t, %1; cvt.u32.u64 %0, t; }" : "=r"(a) : "l"(p));
    return a;
}
#define LDSM_X4(r0, r1, r2, r3, addr) \
    asm volatile("ldmatrix.sync.aligned.m8n8.x4.shared.b16 {%0,%1,%2,%3}, [%4];" \
        : "=r"(r0), "=r"(r1), "=r"(r2), "=r"(r3) : "r"(addr))
#define MMA16816(d, a0, a1, a2, a3, b0, b1) \
    asm volatile("mma.sync.aligned.m16n8k16.row.col.f32.bf16.bf16.f32 " \
        "{%0,%1,%2,%3},{%4,%5,%6,%7},{%8,%9},{%0,%1,%2,%3};" \
        : "+f"((d)[0]), "+f"((d)[1]), "+f"((d)[2]), "+f"((d)[3]) \
        : "r"(a0), "r"(a1), "r"(a2), "r"(a3), "r"(b0), "r"(b1))
__device__ __forceinline__ void cp16(uint32_t dst, const void* src) {
    asm volatile("cp.async.cg.shared.global [%0], [%1], 16;" :: "r"(dst), "l"(src));
}
#define CP_COMMIT() asm volatile("cp.async.commit_group;" ::: "memory")

__device__ __forceinline__ int edge_at(const void* ei, int is64, size_t idx) {
    return is64 ? (int)((const long long*)ei)[idx] : ((const int*)ei)[idx];
}

// fp16 pair accumulate: acc += convert(u) * wt
__device__ __forceinline__ void acc_h4(float4& acc, uint2 u, float wt) {
    float2 f0 = __half22float2(*(const __half2*)&u.x);
    float2 f1 = __half22float2(*(const __half2*)&u.y);
    acc.x = fmaf(f0.x, wt, acc.x);
    acc.y = fmaf(f0.y, wt, acc.y);
    acc.z = fmaf(f1.x, wt, acc.z);
    acc.w = fmaf(f1.y, wt, acc.w);
}

// ---------------- CSR build ----------------
__global__ void k_hist(const void* __restrict__ ei, int E) {
    int e = blockIdx.x * blockDim.x + threadIdx.x;
    int is64 = g_is64;
    if (e < E) atomicAdd(&g_deg[edge_at(ei, is64, (size_t)E + e)], 1);
}
// block reduction + last-block exclusive scan of the 128 block sums
__global__ void k_scanA() {
    __shared__ int s[256];
    __shared__ int isLast;
    int b = blockIdx.x, t = threadIdx.x;
    s[t] = g_deg[b * 256 + t];
    __syncthreads();
    for (int o = 128; o > 0; o >>= 1) {
        if (t < o) s[t] += s[t + o];
        __syncthreads();
    }
    if (t == 0) {
        g_bsum[b] = s[0];
        __threadfence();
        isLast = (atomicAdd(&g_scnt, 1) == 127);
    }
    __syncthreads();
    if (isLast) {
        int v = (t < 128) ? g_bsum[t] : 0;
        s[t] = v;
        __syncthreads();
        for (int off = 1; off < 128; off <<= 1) {
            int x = (t >= off) ? s[t - off] : 0;
            __syncthreads();
            s[t] += x;
            __syncthreads();
        }
        if (t < 128) g_bsum[t] = s[t] - v;
        if (t == 127) g_rowptr[NN] = s[127];
    }
}
__global__ void k_scan3() {
    __shared__ int s[256];
    int b = blockIdx.x, t = threadIdx.x;
    int i = b * 256 + t;
    int v = g_deg[i];
    s[t] = v;
    __syncthreads();
    for (int off = 1; off < 256; off <<= 1) {
        int x = (t >= off) ? s[t - off] : 0;
        __syncthreads();
        s[t] += x;
        __syncthreads();
    }
    int excl = s[t] - v + g_bsum[b];
    g_rowptr[i] = excl;
    g_cursor[i] = excl;
}
__global__ void k_scatter(const void* __restrict__ ei, int E) {
    int e = blockIdx.x * blockDim.x + threadIdx.x;
    int is64 = g_is64;
    if (e < E) {
        int s = edge_at(ei, is64, e);
        int d = edge_at(ei, is64, (size_t)E + e);
        g_csr[atomicAdd(&g_cursor[d], 1)] = s;
    } else if (e < E + NN) {
        int n = e - E;
        g_csr[atomicAdd(&g_cursor[n], 1)] = n;
    }
}

// ---------------- conv (+BN from raw stats) + weight prep, merged ------------
// blocks [0, convBlocks): activation fp32 -> (BN+ReLU) -> bf16 hi/lo split.
// blocks [convBlocks, ...): W[K,Nn] transpose + bf16 split into g_Bhi/g_Blo.
// INIT (layer 1 only): deg init, scan counter reset, dtype detect (block 0).
template <bool FUSE, bool INIT>
__global__ void __launch_bounds__(256) k_convprep(
    const float4* __restrict__ src, int kmask4, int convBlocks,
    const float* __restrict__ W, int K, int Nn,
    const float* __restrict__ gamma, const float* __restrict__ beta,
    const unsigned int* __restrict__ ei32)
{
    const int tid = threadIdx.x;
    if ((int)blockIdx.x < convBlocks) {
        __shared__ float s_sc[CC], s_sh[CC];
        __shared__ unsigned int s_or[256];
        int i = blockIdx.x * 256 + tid;
        if (FUSE) {
            if (tid < CC) {
                float mu = g_bnsum[tid] * (1.f / NN);
                float var = g_bnsq[tid] * (1.f / NN) - mu * mu;
                float sc = gamma[tid] * rsqrtf(var + 1e-5f);
                s_sc[tid] = sc;
                s_sh[tid] = beta[tid] - mu * sc;
            }
            __syncthreads();
        }
        if (INIT) {
            if (i < NN) g_deg[i] = 1;
            if (i == 0) g_scnt = 0;
            if (blockIdx.x == 0) {
                unsigned int v = 0;
#pragma unroll
                for (int k = 0; k < 8; k++) v |= ei32[2 * (tid * 8 + k) + 1];
                s_or[tid] = v;
                __syncthreads();
                for (int o = 128; o > 0; o >>= 1) {
                    if (tid < o) s_or[tid] |= s_or[tid + o];
                    __syncthreads();
                }
                if (tid == 0) g_is64 = (s_or[0] == 0) ? 1 : 0;
            }
        }
        if (i < NN * HH) { g_asrc[i] = 0.f; g_adst[i] = 0.f; }
        float4 v = src[i];
        if (FUSE) {
            int ch = (i & kmask4) * 4;
            v.x = fmaxf(fmaf(v.x, s_sc[ch + 0], s_sh[ch + 0]), 0.f);
            v.y = fmaxf(fmaf(v.y, s_sc[ch + 1], s_sh[ch + 1]), 0.f);
            v.z = fmaxf(fmaf(v.z, s_sc[ch + 2], s_sh[ch + 2]), 0.f);
            v.w = fmaxf(fmaf(v.w, s_sc[ch + 3], s_sh[ch + 3]), 0.f);
        }
        __nv_bfloat162 h0 = __floats2bfloat162_rn(v.x, v.y);
        __nv_bfloat162 h1 = __floats2bfloat162_rn(v.z, v.w);
        __nv_bfloat162 l0 = __floats2bfloat162_rn(v.x - __bfloat162float(h0.x),
                                                  v.y - __bfloat162float(h0.y));
        __nv_bfloat162 l1 = __floats2bfloat162_rn(v.z - __bfloat162float(h1.x),
                                                  v.w - __bfloat162float(h1.y));
        *(uint2*)&g_Ahi[(size_t)i * 4] = make_uint2(*(uint32_t*)&h0, *(uint32_t*)&h1);
        *(uint2*)&g_Alo[(size_t)i * 4] = make_uint2(*(uint32_t*)&l0, *(uint32_t*)&l1);
    } else {
        __shared__ float tile[32][33];
        int pb = blockIdx.x - convBlocks;
        int nb = (pb % (Nn / 32)) * 32;
        int kb = (pb / (Nn / 32)) * 32;
        int tx = tid & 31, ty = tid >> 5;
        for (int j = ty; j < 32; j += 8)
            tile[j][tx] = W[(size_t)(kb + j) * Nn + nb + tx];
        __syncthreads();
        for (int j = ty; j < 32; j += 8) {
            float v = tile[tx][j];
            __nv_bfloat16 hi = __float2bfloat16_rn(v);
            __nv_bfloat16 lo = __float2bfloat16_rn(v - __bfloat162float(hi));
            size_t o = (size_t)(nb + j) * K + kb + tx;
            g_Bhi[o] = hi;
            g_Blo[o] = lo;
        }
    }
}

// ---------------- cp.async double-buffered bf16 mma GEMM ----------------
template <int K, bool ATTN, bool OUTF32>
__global__ void __launch_bounds__(256, 2) k_gemm_m(
    float* __restrict__ C, int Nn,
    const float* __restrict__ attS, const float* __restrict__ attD,
    const float* __restrict__ bias)
{
    constexpr int NC = K / 32;
    constexpr uint32_t STG = 40960;
    constexpr uint32_t OFF_AL = 10240, OFF_BH = 20480, OFF_BL = 30720;
    extern __shared__ __align__(16) char smraw[];
    const uint32_t sb = smem_u32(smraw);

    const int tid = threadIdx.x;
    const int lane = tid & 31;
    const int wid = tid >> 5;
    const int wm = wid & 3, wn = wid >> 2;
    const int row0 = blockIdx.y * 128, col0 = blockIdx.x * 128;

    float d[2][8][4];
#pragma unroll
    for (int i = 0; i < 2; i++)
#pragma unroll
        for (int j = 0; j < 8; j++)
#pragma unroll
            for (int q = 0; q < 4; q++) d[i][j][q] = 0.f;

    const int c0 = tid, c1 = tid + 256;
    const int r0s = c0 >> 2, kb0 = c0 & 3;
    const int r1s = c1 >> 2, kb1 = c1 & 3;

#define STAGE(kc, s) do { \
    uint32_t b = sb + (s) * STG; \
    cp16(b + r0s * 80 + kb0 * 16, &g_Ahi[(size_t)(row0 + r0s) * K + (kc) * 32 + kb0 * 8]); \
    cp16(b + r1s * 80 + kb1 * 16, &g_Ahi[(size_t)(row0 + r1s) * K + (kc) * 32 + kb1 * 8]); \
    cp16(b + OFF_AL + r0s * 80 + kb0 * 16, &g_Alo[(size_t)(row0 + r0s) * K + (kc) * 32 + kb0 * 8]); \
    cp16(b + OFF_AL + r1s * 80 + kb1 * 16, &g_Alo[(size_t)(row0 + r1s) * K + (kc) * 32 + kb1 * 8]); \
    cp16(b + OFF_BH + r0s * 80 + kb0 * 16, &g_Bhi[(size_t)(col0 + r0s) * K + (kc) * 32 + kb0 * 8]); \
    cp16(b + OFF_BH + r1s * 80 + kb1 * 16, &g_Bhi[(size_t)(col0 + r1s) * K + (kc) * 32 + kb1 * 8]); \
    cp16(b + OFF_BL + r0s * 80 + kb0 * 16, &g_Blo[(size_t)(col0 + r0s) * K + (kc) * 32 + kb0 * 8]); \
    cp16(b + OFF_BL + r1s * 80 + kb1 * 16, &g_Blo[(size_t)(col0 + r1s) * K + (kc) * 32 + kb1 * 8]); \
} while (0)

    STAGE(0, 0);
    CP_COMMIT();

    const int a_row = lane & 15, a_col8 = (lane >> 4) * 8;
    const int b_row = ((lane >> 4) << 3) + (lane & 7), b_col8 = ((lane >> 3) & 1) * 8;

    for (int kc = 0; kc < NC; ++kc) {
        if (kc + 1 < NC) {
            STAGE(kc + 1, (kc + 1) & 1);
            CP_COMMIT();
            asm volatile("cp.async.wait_group 1;" ::: "memory");
        } else {
            asm volatile("cp.async.wait_group 0;" ::: "memory");
        }
        __syncthreads();

        const uint32_t bs = sb + (kc & 1) * STG;
#pragma unroll
        for (int kk = 0; kk < 32; kk += 16) {
            uint32_t ah[2][4], al[2][4], bh[8][2], bl[8][2];
#pragma unroll
            for (int mi = 0; mi < 2; mi++) {
                uint32_t off = (uint32_t)((wm * 32 + mi * 16 + a_row) * 40 + kk + a_col8) * 2;
                LDSM_X4(ah[mi][0], ah[mi][1], ah[mi][2], ah[mi][3], bs + off);
                LDSM_X4(al[mi][0], al[mi][1], al[mi][2], al[mi][3], bs + OFF_AL + off);
            }
#pragma unroll
            for (int np = 0; np < 4; np++) {
                uint32_t off = (uint32_t)((wn * 64 + np * 16 + b_row) * 40 + kk + b_col8) * 2;
                uint32_t r0, r1, r2, r3;
                LDSM_X4(r0, r1, r2, r3, bs + OFF_BH + off);
                bh[np * 2][0] = r0; bh[np * 2][1] = r1;
                bh[np * 2 + 1][0] = r2; bh[np * 2 + 1][1] = r3;
                LDSM_X4(r0, r1, r2, r3, bs + OFF_BL + off);
                bl[np * 2][0] = r0; bl[np * 2][1] = r1;
                bl[np * 2 + 1][0] = r2; bl[np * 2 + 1][1] = r3;
            }
#pragma unroll
            for (int mi = 0; mi < 2; mi++)
#pragma unroll
                for (int ni = 0; ni < 8; ni++) {
                    MMA16816(d[mi][ni], ah[mi][0], ah[mi][1], ah[mi][2], ah[mi][3],
                             bh[ni][0], bh[ni][1]);
                    MMA16816(d[mi][ni], ah[mi][0], ah[mi][1], ah[mi][2], ah[mi][3],
                             bl[ni][0], bl[ni][1]);
                    MMA16816(d[mi][ni], al[mi][0], al[mi][1], al[mi][2], al[mi][3],
                             bh[ni][0], bh[ni][1]);
                }
        }
        __syncthreads();
    }
#undef STAGE

    const int er = lane >> 2, ec = (lane & 3) * 2;
#pragma unroll
    for (int mi = 0; mi < 2; mi++) {
        float s0 = 0.f, s1 = 0.f, t0 = 0.f, t1 = 0.f;
#pragma unroll
        for (int ni = 0; ni < 8; ni++) {
            int r = row0 + wm * 32 + mi * 16 + er;
            int c = col0 + wn * 64 + ni * 8 + ec;
            float2 v0 = make_float2(d[mi][ni][0], d[mi][ni][1]);
            float2 v1 = make_float2(d[mi][ni][2], d[mi][ni][3]);
            if (OUTF32) {
                float b0 = __ldg(&bias[c]), b1 = __ldg(&bias[c + 1]);
                v0.x += b0; v0.y += b1; v1.x += b0; v1.y += b1;
                *(float2*)&C[(size_t)r * Nn + c] = v0;
                *(float2*)&C[(size_t)(r + 8) * Nn + c] = v1;
            } else {
                if (ATTN) {
                    int cc = wn * 64 + ni * 8 + ec;
                    int head = blockIdx.x;
                    float a0 = __ldg(&attS[head * CC + cc]);
                    float a1 = __ldg(&attS[head * CC + cc + 1]);
                    float e0 = __ldg(&attD[head * CC + cc]);
                    float e1 = __ldg(&attD[head * CC + cc + 1]);
                    s0 = fmaf(v0.x, a0, fmaf(v0.y, a1, s0));
                    s1 = fmaf(v1.x, a0, fmaf(v1.y, a1, s1));
                    t0 = fmaf(v0.x, e0, fmaf(v0.y, e1, t0));
                    t1 = fmaf(v1.x, e0, fmaf(v1.y, e1, t1));
                }
                *(__half2*)&g_hh[(size_t)r * Nn + c] = __floats2half2_rn(v0.x, v0.y);
                *(__half2*)&g_hh[(size_t)(r + 8) * Nn + c] = __floats2half2_rn(v1.x, v1.y);
            }
        }
        if (ATTN && !OUTF32) {
            s0 += __shfl_xor_sync(0xffffffffu, s0, 1);
            s0 += __shfl_xor_sync(0xffffffffu, s0, 2);
            s1 += __shfl_xor_sync(0xffffffffu, s1, 1);
            s1 += __shfl_xor_sync(0xffffffffu, s1, 2);
            t0 += __shfl_xor_sync(0xffffffffu, t0, 1);
            t0 += __shfl_xor_sync(0xffffffffu, t0, 2);
            t1 += __shfl_xor_sync(0xffffffffu, t1, 1);
            t1 += __shfl_xor_sync(0xffffffffu, t1, 2);
            if ((lane & 3) == 0) {
                int head = blockIdx.x;
                int r = row0 + wm * 32 + mi * 16 + er;
                atomicAdd(&g_asrc[r * 4 + head], s0);
                atomicAdd(&g_adst[r * 4 + head], t0);
                atomicAdd(&g_asrc[(r + 8) * 4 + head], s1);
                atomicAdd(&g_adst[(r + 8) * 4 + head], t1);
            }
        }
    }
}

__device__ __forceinline__ float lrelu(float v) { return v > 0.f ? v : NEG * v; }

// ---------------- per-edge weights (lane-parallel); also zeroes BN stats ----
__global__ void __launch_bounds__(256) k_edgew() {
    if (blockIdx.x == 0 && threadIdx.x < CC) {
        g_bnsum[threadIdx.x] = 0.f;
        g_bnsq[threadIdx.x] = 0.f;
    }
    int lane = threadIdx.x & 31;
    int n = blockIdx.x * 8 + (threadIdx.x >> 5);
    int start = g_rowptr[n], end = g_rowptr[n + 1];
    float4 ad = *(const float4*)&g_adst[n * 4];

    float d0 = 0.f, d1 = 0.f, d2 = 0.f, d3 = 0.f;
    for (int i = start + lane; i < end; i += 32) {
        int s = g_csr[i];
        float4 as = *(const float4*)&g_asrc[s * 4];
        float w0 = __expf(lrelu(as.x + ad.x));
        float w1 = __expf(lrelu(as.y + ad.y));
        float w2 = __expf(lrelu(as.z + ad.z));
        float w3 = __expf(lrelu(as.w + ad.w));
        g_ew[i] = make_float4(w0, w1, w2, w3);
        d0 += w0; d1 += w1; d2 += w2; d3 += w3;
    }
#pragma unroll
    for (int o = 16; o > 0; o >>= 1) {
        d0 += __shfl_xor_sync(0xffffffffu, d0, o);
        d1 += __shfl_xor_sync(0xffffffffu, d1, o);
        d2 += __shfl_xor_sync(0xffffffffu, d2, o);
        d3 += __shfl_xor_sync(0xffffffffu, d3, o);
    }
    if (lane == 0)
        g_dinv[n] = make_float4(1.f / (d0 + 1e-16f), 1.f / (d1 + 1e-16f),
                                1.f / (d2 + 1e-16f), 1.f / (d3 + 1e-16f));
}

// ---------------- aggregation: fp16 gather, 4-edge batched loads ------------
__global__ void __launch_bounds__(256) k_aggr(const __half* __restrict__ h,
                                              const float* __restrict__ bias)
{
    __shared__ float s_sum[CC], s_sq[CC];
    int tid = threadIdx.x;
    if (tid < CC) { s_sum[tid] = 0.f; s_sq[tid] = 0.f; }
    __syncthreads();

    int lane = tid & 31;
    int n = blockIdx.x * 8 + (tid >> 5);
    int start = g_rowptr[n], end = g_rowptr[n + 1];

    const uint2* hp = (const uint2*)h;
    float4 a0 = make_float4(0.f, 0.f, 0.f, 0.f), a1 = a0, a2 = a0, a3 = a0;

    int i = start;
    for (; i + 4 <= end; i += 4) {
        int s0i = g_csr[i], s1i = g_csr[i + 1], s2i = g_csr[i + 2], s3i = g_csr[i + 3];
        float4 w0 = g_ew[i], w1 = g_ew[i + 1], w2 = g_ew[i + 2], w3 = g_ew[i + 3];
        size_t b0 = (size_t)s0i * 128, b1 = (size_t)s1i * 128;
        size_t b2 = (size_t)s2i * 128, b3 = (size_t)s3i * 128;
        uint2 uA0 = hp[b0 + lane],      uA1 = hp[b0 + 32 + lane];
        uint2 uA2 = hp[b0 + 64 + lane], uA3 = hp[b0 + 96 + lane];
        uint2 uB0 = hp[b1 + lane],      uB1 = hp[b1 + 32 + lane];
        uint2 uB2 = hp[b1 + 64 + lane], uB3 = hp[b1 + 96 + lane];
        uint2 uC0 = hp[b2 + lane],      uC1 = hp[b2 + 32 + lane];
        uint2 uC2 = hp[b2 + 64 + lane], uC3 = hp[b2 + 96 + lane];
        uint2 uD0 = hp[b3 + lane],      uD1 = hp[b3 + 32 + lane];
        uint2 uD2 = hp[b3 + 64 + lane], uD3 = hp[b3 + 96 + lane];
        acc_h4(a0, uA0, w0.x); acc_h4(a1, uA1, w0.y); acc_h4(a2, uA2, w0.z); acc_h4(a3, uA3, w0.w);
        acc_h4(a0, uB0, w1.x); acc_h4(a1, uB1, w1.y); acc_h4(a2, uB2, w1.z); acc_h4(a3, uB3, w1.w);
        acc_h4(a0, uC0, w2.x); acc_h4(a1, uC1, w2.y); acc_h4(a2, uC2, w2.z); acc_h4(a3, uC3, w2.w);
        acc_h4(a0, uD0, w3.x); acc_h4(a1, uD1, w3.y); acc_h4(a2, uD2, w3.z); acc_h4(a3, uD3, w3.w);
    }
    for (; i < end; ++i) {
        int s = g_csr[i];
        float4 w = g_ew[i];
        size_t base = (size_t)s * 128;
        uint2 u0 = hp[base + lane];
        uint2 u1 = hp[base + 32 + lane];
        uint2 u2 = hp[base + 64 + lane];
        uint2 u3 = hp[base + 96 + lane];
        acc_h4(a0, u0, w.x); acc_h4(a1, u1, w.y);
        acc_h4(a2, u2, w.z); acc_h4(a3, u3, w.w);
    }
    float4 inv = g_dinv[n];

    float4 bb = ((const float4*)bias)[lane];
    float4 o;
    o.x = 0.25f * (a0.x * inv.x + a1.x * inv.y + a2.x * inv.z + a3.x * inv.w) + bb.x;
    o.y = 0.25f * (a0.y * inv.x + a1.y * inv.y + a2.y * inv.z + a3.y * inv.w) + bb.y;
    o.z = 0.25f * (a0.z * inv.x + a1.z * inv.y + a2.z * inv.z + a3.z * inv.w) + bb.z;
    o.w = 0.25f * (a0.w * inv.x + a1.w * inv.y + a2.w * inv.z + a3.w * inv.w) + bb.w;
    ((float4*)g_t)[(size_t)n * 32 + lane] = o;

    int c = lane * 4;
    atomicAdd(&s_sum[c + 0], o.x); atomicAdd(&s_sq[c + 0], o.x * o.x);
    atomicAdd(&s_sum[c + 1], o.y); atomicAdd(&s_sq[c + 1], o.y * o.y);
    atomicAdd(&s_sum[c + 2], o.z); atomicAdd(&s_sq[c + 2], o.z * o.z);
    atomicAdd(&s_sum[c + 3], o.w); atomicAdd(&s_sq[c + 3], o.w * o.w);
    __syncthreads();
    if (tid < CC) {
        atomicAdd(&g_bnsum[tid], s_sum[tid]);
        atomicAdd(&g_bnsq[tid], s_sq[tid]);
    }
}

// ---------------- launch ----------------
extern "C" void kernel_launch(void* const* d_in, const int* in_sizes, int n_in,
                              void* d_out, int out_size)
{
    const float* x   = (const float*)d_in[0];
    const void*  ei  = d_in[1];
    const float* W1  = (const float*)d_in[2];
    const float* as1 = (const float*)d_in[3];
    const float* ad1 = (const float*)d_in[4];
    const float* b1  = (const float*)d_in[5];
    const float* g1  = (const float*)d_in[6];
    const float* be1 = (const float*)d_in[7];
    const float* W2  = (const float*)d_in[8];
    const float* as2 = (const float*)d_in[9];
    const float* ad2 = (const float*)d_in[10];
    const float* b2  = (const float*)d_in[11];
    const float* g2  = (const float*)d_in[12];
    const float* be2 = (const float*)d_in[13];
    const float* Wf  = (const float*)d_in[14];
    const float* bf  = (const float*)d_in[15];
    int E = in_sizes[1] / 2;

    __half* phh = nullptr;
    float* pt = nullptr;
    cudaGetSymbolAddress((void**)&phh, g_hh);
    cudaGetSymbolAddress((void**)&pt, g_t);
    float* out = (float*)d_out;

    constexpr int SMEM = 81920;
    cudaFuncSetAttribute(k_gemm_m<256, true, false>,
                         cudaFuncAttributeMaxDynamicSharedMemorySize, SMEM);
    cudaFuncSetAttribute(k_gemm_m<128, true, false>,
                         cudaFuncAttributeMaxDynamicSharedMemorySize, SMEM);
    cudaFuncSetAttribute(k_gemm_m<128, false, true>,
                         cudaFuncAttributeMaxDynamicSharedMemorySize, SMEM);

    // layer 1: conv+prep (+init/detect), gemm
    k_convprep<false, true><<<8192 + 128, 256>>>(
        (const float4*)x, FIN / 4 - 1, 8192, W1, FIN, HC, nullptr, nullptr,
        (const unsigned int*)ei);
    k_gemm_m<256, true, false><<<dim3(4, 256), 256, SMEM>>>(nullptr, HC, as1, ad1, nullptr);

    // CSR build
    k_hist<<<(E + 255) / 256, 256>>>(ei, E);
    k_scanA<<<128, 256>>>();
    k_scan3<<<128, 256>>>();
    k_scatter<<<(E + NN + 255) / 256, 256>>>(ei, E);

    k_edgew<<<4096, 256>>>();
    k_aggr<<<4096, 256>>>(phh, b1);

    // layer 2
    k_convprep<true, false><<<4096 + 64, 256>>>(
        (const float4*)pt, CC / 4 - 1, 4096, W2, CC, HC, g1, be1, nullptr);
    k_gemm_m<128, true, false><<<dim3(4, 256), 256, SMEM>>>(nullptr, HC, as2, ad2, nullptr);
    k_edgew<<<4096, 256>>>();
    k_aggr<<<4096, 256>>>(phh, b2);

    // final linear (fp32 out)
    k_convprep<true, false><<<4096 + 16, 256>>>(
        (const float4*)pt, CC / 4 - 1, 4096, Wf, CC, CC, g2, be2, nullptr);
    k_gemm_m<128, false, true><<<dim3(1, 256), 256, SMEM>>>(out, CC, nullptr, nullptr, bf);
}

// round 16
// speedup vs baseline: 1.3104x; 1.0770x over previous
#include <cuda_runtime.h>
#include <cuda_bf16.h>
#include <cuda_fp16.h>
#include <cstdint>

#define NN    32768
#define FIN   256
#define HH    4
#define CC    128
#define HC    512
#define EMAX  524288
#define NEG   0.2f

// ---------------- scratch ----------------
__device__ __half g_hh[(size_t)NN * HC];   // post-GEMM features fp16 (gather src)
__device__ float g_t[(size_t)NN * CC];
__device__ float g_asrc[NN * HH];
__device__ float g_adst[NN * HH];
__device__ int   g_deg[NN];
__device__ int   g_rowptr[NN + 1];
__device__ int   g_cursor[NN];
__device__ int   g_csr[EMAX + NN];
__device__ float g_bnsumA[CC], g_bnsqA[CC];   // BN stats, layer-1 slot
__device__ float g_bnsumB[CC], g_bnsqB[CC];   // BN stats, layer-2 slot
__device__ int   g_is64;
__device__ int   g_scnt;
__device__ int   g_bsum[128];
__device__ __nv_bfloat16 g_Bhi[HC * FIN];
__device__ __nv_bfloat16 g_Blo[HC * FIN];
__device__ __nv_bfloat16 g_Ahi[(size_t)NN * FIN];
__device__ __nv_bfloat16 g_Alo[(size_t)NN * FIN];

__device__ __forceinline__ uint32_t smem_u32(const void* p) {
    uint32_t a;
    asm("{ .reg .u64 t; cvta.to.shared.u64 t, %1; cvt.u32.u64 %0, t; }" : "=r"(a) : "l"(p));
    return a;
}
#define LDSM_X4(r0, r1, r2, r3, addr) \
    asm volatile("ldmatrix.sync.aligned.m8n8.x4.shared.b16 {%0,%1,%2,%3}, [%4];" \
        : "=r"(r0), "=r"(r1), "=r"(r2), "=r"(r3) : "r"(addr))
#define MMA16816(d, a0, a1, a2, a3, b0, b1) \
    asm volatile("mma.sync.aligned.m16n8k16.row.col.f32.bf16.bf16.f32 " \
        "{%0,%1,%2,%3},{%4,%5,%6,%7},{%8,%9},{%0,%1,%2,%3};" \
        : "+f"((d)[0]), "+f"((d)[1]), "+f"((d)[2]), "+f"((d)[3]) \
        : "r"(a0), "r"(a1), "r"(a2), "r"(a3), "r"(b0), "r"(b1))
__device__ __forceinline__ void cp16(uint32_t dst, const void* src) {
    asm volatile("cp.async.cg.shared.global [%0], [%1], 16;" :: "r"(dst), "l"(src));
}
#define CP_COMMIT() asm volatile("cp.async.commit_group;" ::: "memory")

__device__ __forceinline__ int edge_at(const void* ei, int is64, size_t idx) {
    return is64 ? (int)((const long long*)ei)[idx] : ((const int*)ei)[idx];
}

__device__ __forceinline__ void acc_h4(float4& acc, uint2 u, float wt) {
    float2 f0 = __half22float2(*(const __half2*)&u.x);
    float2 f1 = __half22float2(*(const __half2*)&u.y);
    acc.x = fmaf(f0.x, wt, acc.x);
    acc.y = fmaf(f0.y, wt, acc.y);
    acc.z = fmaf(f1.x, wt, acc.z);
    acc.w = fmaf(f1.y, wt, acc.w);
}

__device__ __forceinline__ float lrelu(float v) { return v > 0.f ? v : NEG * v; }

// ---------------- CSR build ----------------
__global__ void k_hist(const void* __restrict__ ei, int E) {
    int e = blockIdx.x * blockDim.x + threadIdx.x;
    int is64 = g_is64;
    if (e < E) atomicAdd(&g_deg[edge_at(ei, is64, (size_t)E + e)], 1);
}
__global__ void k_scanA() {
    __shared__ int s[256];
    __shared__ int isLast;
    int b = blockIdx.x, t = threadIdx.x;
    s[t] = g_deg[b * 256 + t];
    __syncthreads();
    for (int o = 128; o > 0; o >>= 1) {
        if (t < o) s[t] += s[t + o];
        __syncthreads();
    }
    if (t == 0) {
        g_bsum[b] = s[0];
        __threadfence();
        isLast = (atomicAdd(&g_scnt, 1) == 127);
    }
    __syncthreads();
    if (isLast) {
        int v = (t < 128) ? g_bsum[t] : 0;
        s[t] = v;
        __syncthreads();
        for (int off = 1; off < 128; off <<= 1) {
            int x = (t >= off) ? s[t - off] : 0;
            __syncthreads();
            s[t] += x;
            __syncthreads();
        }
        if (t < 128) g_bsum[t] = s[t] - v;
        if (t == 127) g_rowptr[NN] = s[127];
    }
}
__global__ void k_scan3() {
    __shared__ int s[256];
    int b = blockIdx.x, t = threadIdx.x;
    int i = b * 256 + t;
    int v = g_deg[i];
    s[t] = v;
    __syncthreads();
    for (int off = 1; off < 256; off <<= 1) {
        int x = (t >= off) ? s[t - off] : 0;
        __syncthreads();
        s[t] += x;
        __syncthreads();
    }
    int excl = s[t] - v + g_bsum[b];
    g_rowptr[i] = excl;
    g_cursor[i] = excl;
}
__global__ void k_scatter(const void* __restrict__ ei, int E) {
    int e = blockIdx.x * blockDim.x + threadIdx.x;
    int is64 = g_is64;
    if (e < E) {
        int s = edge_at(ei, is64, e);
        int d = edge_at(ei, is64, (size_t)E + e);
        g_csr[atomicAdd(&g_cursor[d], 1)] = s;
    } else if (e < E + NN) {
        int n = e - E;
        g_csr[atomicAdd(&g_cursor[n], 1)] = n;
    }
}

// ---------------- conv (+BN) + weight prep, merged ----------------
template <bool FUSE, bool INIT>
__global__ void __launch_bounds__(256) k_convprep(
    const float4* __restrict__ src, int kmask4, int convBlocks,
    const float* __restrict__ W, int K, int Nn,
    const float* __restrict__ gamma, const float* __restrict__ beta,
    const float* __restrict__ bnsum, const float* __restrict__ bnsq,
    const unsigned int* __restrict__ ei32)
{
    const int tid = threadIdx.x;
    if ((int)blockIdx.x < convBlocks) {
        __shared__ float s_sc[CC], s_sh[CC];
        __shared__ unsigned int s_or[256];
        int i = blockIdx.x * 256 + tid;
        if (FUSE) {
            if (tid < CC) {
                float mu = bnsum[tid] * (1.f / NN);
                float var = bnsq[tid] * (1.f / NN) - mu * mu;
                float sc = gamma[tid] * rsqrtf(var + 1e-5f);
                s_sc[tid] = sc;
                s_sh[tid] = beta[tid] - mu * sc;
            }
            __syncthreads();
        }
        if (INIT) {
            if (i < NN) g_deg[i] = 1;
            if (i == 0) g_scnt = 0;
            if (blockIdx.x == 0) {
                if (tid < CC) {
                    g_bnsumA[tid] = 0.f; g_bnsqA[tid] = 0.f;
                    g_bnsumB[tid] = 0.f; g_bnsqB[tid] = 0.f;
                }
                unsigned int v = 0;
#pragma unroll
                for (int k = 0; k < 8; k++) v |= ei32[2 * (tid * 8 + k) + 1];
                s_or[tid] = v;
                __syncthreads();
                for (int o = 128; o > 0; o >>= 1) {
                    if (tid < o) s_or[tid] |= s_or[tid + o];
                    __syncthreads();
                }
                if (tid == 0) g_is64 = (s_or[0] == 0) ? 1 : 0;
            }
        }
        if (i < NN * HH) { g_asrc[i] = 0.f; g_adst[i] = 0.f; }
        float4 v = src[i];
        if (FUSE) {
            int ch = (i & kmask4) * 4;
            v.x = fmaxf(fmaf(v.x, s_sc[ch + 0], s_sh[ch + 0]), 0.f);
            v.y = fmaxf(fmaf(v.y, s_sc[ch + 1], s_sh[ch + 1]), 0.f);
            v.z = fmaxf(fmaf(v.z, s_sc[ch + 2], s_sh[ch + 2]), 0.f);
            v.w = fmaxf(fmaf(v.w, s_sc[ch + 3], s_sh[ch + 3]), 0.f);
        }
        __nv_bfloat162 h0 = __floats2bfloat162_rn(v.x, v.y);
        __nv_bfloat162 h1 = __floats2bfloat162_rn(v.z, v.w);
        __nv_bfloat162 l0 = __floats2bfloat162_rn(v.x - __bfloat162float(h0.x),
                                                  v.y - __bfloat162float(h0.y));
        __nv_bfloat162 l1 = __floats2bfloat162_rn(v.z - __bfloat162float(h1.x),
                                                  v.w - __bfloat162float(h1.y));
        *(uint2*)&g_Ahi[(size_t)i * 4] = make_uint2(*(uint32_t*)&h0, *(uint32_t*)&h1);
        *(uint2*)&g_Alo[(size_t)i * 4] = make_uint2(*(uint32_t*)&l0, *(uint32_t*)&l1);
    } else {
        __shared__ float tile[32][33];
        int pb = blockIdx.x - convBlocks;
        int nb = (pb % (Nn / 32)) * 32;
        int kb = (pb / (Nn / 32)) * 32;
        int tx = tid & 31, ty = tid >> 5;
        for (int j = ty; j < 32; j += 8)
            tile[j][tx] = W[(size_t)(kb + j) * Nn + nb + tx];
        __syncthreads();
        for (int j = ty; j < 32; j += 8) {
            float v = tile[tx][j];
            __nv_bfloat16 hi = __float2bfloat16_rn(v);
            __nv_bfloat16 lo = __float2bfloat16_rn(v - __bfloat162float(hi));
            size_t o = (size_t)(nb + j) * K + kb + tx;
            g_Bhi[o] = hi;
            g_Blo[o] = lo;
        }
    }
}

// ---------------- cp.async double-buffered bf16 mma GEMM ----------------
template <int K, bool ATTN, bool OUTF32>
__global__ void __launch_bounds__(256, 2) k_gemm_m(
    float* __restrict__ C, int Nn,
    const float* __restrict__ attS, const float* __restrict__ attD,
    const float* __restrict__ bias)
{
    constexpr int NC = K / 32;
    constexpr uint32_t STG = 40960;
    constexpr uint32_t OFF_AL = 10240, OFF_BH = 20480, OFF_BL = 30720;
    extern __shared__ __align__(16) char smraw[];
    const uint32_t sb = smem_u32(smraw);

    const int tid = threadIdx.x;
    const int lane = tid & 31;
    const int wid = tid >> 5;
    const int wm = wid & 3, wn = wid >> 2;
    const int row0 = blockIdx.y * 128, col0 = blockIdx.x * 128;

    float d[2][8][4];
#pragma unroll
    for (int i = 0; i < 2; i++)
#pragma unroll
        for (int j = 0; j < 8; j++)
#pragma unroll
            for (int q = 0; q < 4; q++) d[i][j][q] = 0.f;

    const int c0 = tid, c1 = tid + 256;
    const int r0s = c0 >> 2, kb0 = c0 & 3;
    const int r1s = c1 >> 2, kb1 = c1 & 3;

#define STAGE(kc, s) do { \
    uint32_t b = sb + (s) * STG; \
    cp16(b + r0s * 80 + kb0 * 16, &g_Ahi[(size_t)(row0 + r0s) * K + (kc) * 32 + kb0 * 8]); \
    cp16(b + r1s * 80 + kb1 * 16, &g_Ahi[(size_t)(row0 + r1s) * K + (kc) * 32 + kb1 * 8]); \
    cp16(b + OFF_AL + r0s * 80 + kb0 * 16, &g_Alo[(size_t)(row0 + r0s) * K + (kc) * 32 + kb0 * 8]); \
    cp16(b + OFF_AL + r1s * 80 + kb1 * 16, &g_Alo[(size_t)(row0 + r1s) * K + (kc) * 32 + kb1 * 8]); \
    cp16(b + OFF_BH + r0s * 80 + kb0 * 16, &g_Bhi[(size_t)(col0 + r0s) * K + (kc) * 32 + kb0 * 8]); \
    cp16(b + OFF_BH + r1s * 80 + kb1 * 16, &g_Bhi[(size_t)(col0 + r1s) * K + (kc) * 32 + kb1 * 8]); \
    cp16(b + OFF_BL + r0s * 80 + kb0 * 16, &g_Blo[(size_t)(col0 + r0s) * K + (kc) * 32 + kb0 * 8]); \
    cp16(b + OFF_BL + r1s * 80 + kb1 * 16, &g_Blo[(size_t)(col0 + r1s) * K + (kc) * 32 + kb1 * 8]); \
} while (0)

    STAGE(0, 0);
    CP_COMMIT();

    const int a_row = lane & 15, a_col8 = (lane >> 4) * 8;
    const int b_row = ((lane >> 4) << 3) + (lane & 7), b_col8 = ((lane >> 3) & 1) * 8;

    for (int kc = 0; kc < NC; ++kc) {
        if (kc + 1 < NC) {
            STAGE(kc + 1, (kc + 1) & 1);
            CP_COMMIT();
            asm volatile("cp.async.wait_group 1;" ::: "memory");
        } else {
            asm volatile("cp.async.wait_group 0;" ::: "memory");
        }
        __syncthreads();

        const uint32_t bs = sb + (kc & 1) * STG;
#pragma unroll
        for (int kk = 0; kk < 32; kk += 16) {
            uint32_t ah[2][4], al[2][4], bh[8][2], bl[8][2];
#pragma unroll
            for (int mi = 0; mi < 2; mi++) {
                uint32_t off = (uint32_t)((wm * 32 + mi * 16 + a_row) * 40 + kk + a_col8) * 2;
                LDSM_X4(ah[mi][0], ah[mi][1], ah[mi][2], ah[mi][3], bs + off);
                LDSM_X4(al[mi][0], al[mi][1], al[mi][2], al[mi][3], bs + OFF_AL + off);
            }
#pragma unroll
            for (int np = 0; np < 4; np++) {
                uint32_t off = (uint32_t)((wn * 64 + np * 16 + b_row) * 40 + kk + b_col8) * 2;
                uint32_t r0, r1, r2, r3;
                LDSM_X4(r0, r1, r2, r3, bs + OFF_BH + off);
                bh[np * 2][0] = r0; bh[np * 2][1] = r1;
                bh[np * 2 + 1][0] = r2; bh[np * 2 + 1][1] = r3;
                LDSM_X4(r0, r1, r2, r3, bs + OFF_BL + off);
                bl[np * 2][0] = r0; bl[np * 2][1] = r1;
                bl[np * 2 + 1][0] = r2; bl[np * 2 + 1][1] = r3;
            }
#pragma unroll
            for (int mi = 0; mi < 2; mi++)
#pragma unroll
                for (int ni = 0; ni < 8; ni++) {
                    MMA16816(d[mi][ni], ah[mi][0], ah[mi][1], ah[mi][2], ah[mi][3],
                             bh[ni][0], bh[ni][1]);
                    MMA16816(d[mi][ni], ah[mi][0], ah[mi][1], ah[mi][2], ah[mi][3],
                             bl[ni][0], bl[ni][1]);
                    MMA16816(d[mi][ni], al[mi][0], al[mi][1], al[mi][2], al[mi][3],
                             bh[ni][0], bh[ni][1]);
                }
        }
        __syncthreads();
    }
#undef STAGE

    const int er = lane >> 2, ec = (lane & 3) * 2;
#pragma unroll
    for (int mi = 0; mi < 2; mi++) {
        float s0 = 0.f, s1 = 0.f, t0 = 0.f, t1 = 0.f;
#pragma unroll
        for (int ni = 0; ni < 8; ni++) {
            int r = row0 + wm * 32 + mi * 16 + er;
            int c = col0 + wn * 64 + ni * 8 + ec;
            float2 v0 = make_float2(d[mi][ni][0], d[mi][ni][1]);
            float2 v1 = make_float2(d[mi][ni][2], d[mi][ni][3]);
            if (OUTF32) {
                float b0 = __ldg(&bias[c]), b1 = __ldg(&bias[c + 1]);
                v0.x += b0; v0.y += b1; v1.x += b0; v1.y += b1;
                *(float2*)&C[(size_t)r * Nn + c] = v0;
                *(float2*)&C[(size_t)(r + 8) * Nn + c] = v1;
            } else {
                if (ATTN) {
                    int cc = wn * 64 + ni * 8 + ec;
                    int head = blockIdx.x;
                    float a0 = __ldg(&attS[head * CC + cc]);
                    float a1 = __ldg(&attS[head * CC + cc + 1]);
                    float e0 = __ldg(&attD[head * CC + cc]);
                    float e1 = __ldg(&attD[head * CC + cc + 1]);
                    s0 = fmaf(v0.x, a0, fmaf(v0.y, a1, s0));
                    s1 = fmaf(v1.x, a0, fmaf(v1.y, a1, s1));
                    t0 = fmaf(v0.x, e0, fmaf(v0.y, e1, t0));
                    t1 = fmaf(v1.x, e0, fmaf(v1.y, e1, t1));
                }
                *(__half2*)&g_hh[(size_t)r * Nn + c] = __floats2half2_rn(v0.x, v0.y);
                *(__half2*)&g_hh[(size_t)(r + 8) * Nn + c] = __floats2half2_rn(v1.x, v1.y);
            }
        }
        if (ATTN && !OUTF32) {
            s0 += __shfl_xor_sync(0xffffffffu, s0, 1);
            s0 += __shfl_xor_sync(0xffffffffu, s0, 2);
            s1 += __shfl_xor_sync(0xffffffffu, s1, 1);
            s1 += __shfl_xor_sync(0xffffffffu, s1, 2);
            t0 += __shfl_xor_sync(0xffffffffu, t0, 1);
            t0 += __shfl_xor_sync(0xffffffffu, t0, 2);
            t1 += __shfl_xor_sync(0xffffffffu, t1, 1);
            t1 += __shfl_xor_sync(0xffffffffu, t1, 2);
            if ((lane & 3) == 0) {
                int head = blockIdx.x;
                int r = row0 + wm * 32 + mi * 16 + er;
                atomicAdd(&g_asrc[r * 4 + head], s0);
                atomicAdd(&g_adst[r * 4 + head], t0);
                atomicAdd(&g_asrc[(r + 8) * 4 + head], s1);
                atomicAdd(&g_adst[(r + 8) * 4 + head], t1);
            }
        }
    }
}

// ---------------- merged edge-weights + aggregation ----------------
// warp per node. Per 32-edge chunk: lanes compute weights (one exp per
// edge-head) into smem; then the 4-edge-batched fp16 gather reads weights
// from smem. Denominator reduced at end (no g_ew / g_dinv globals).
__global__ void __launch_bounds__(256) k_aggr(const __half* __restrict__ h,
                                              const float* __restrict__ bias,
                                              float* __restrict__ bnsum,
                                              float* __restrict__ bnsq)
{
    __shared__ float s_sum[CC], s_sq[CC];
    __shared__ __align__(16) float4 s_w[8][32];
    __shared__ int s_idx[8][32];
    int tid = threadIdx.x;
    if (tid < CC) { s_sum[tid] = 0.f; s_sq[tid] = 0.f; }
    __syncthreads();

    int lane = tid & 31;
    int wp = tid >> 5;
    int n = blockIdx.x * 8 + wp;
    int start = g_rowptr[n], end = g_rowptr[n + 1];
    float4 ad = *(const float4*)&g_adst[n * 4];

    const uint2* hp = (const uint2*)h;
    float4 a0 = make_float4(0.f, 0.f, 0.f, 0.f), a1 = a0, a2 = a0, a3 = a0;
    float d0 = 0.f, d1 = 0.f, d2 = 0.f, d3 = 0.f;

    for (int i = start; i < end; i += 32) {
        int cnt = min(32, end - i);
        float4 wv = make_float4(0.f, 0.f, 0.f, 0.f);
        int sidx = 0;
        if (lane < cnt) {
            sidx = g_csr[i + lane];
            float4 as = *(const float4*)&g_asrc[sidx * 4];
            wv.x = __expf(lrelu(as.x + ad.x));
            wv.y = __expf(lrelu(as.y + ad.y));
            wv.z = __expf(lrelu(as.z + ad.z));
            wv.w = __expf(lrelu(as.w + ad.w));
        }
        d0 += wv.x; d1 += wv.y; d2 += wv.z; d3 += wv.w;
        s_w[wp][lane] = wv;
        s_idx[wp][lane] = sidx;
        __syncwarp();

        int j = 0;
        for (; j + 4 <= cnt; j += 4) {
            int p0 = s_idx[wp][j], p1 = s_idx[wp][j + 1];
            int p2 = s_idx[wp][j + 2], p3 = s_idx[wp][j + 3];
            float4 w0 = s_w[wp][j], w1 = s_w[wp][j + 1];
            float4 w2 = s_w[wp][j + 2], w3 = s_w[wp][j + 3];
            size_t b0 = (size_t)p0 * 128, b1 = (size_t)p1 * 128;
            size_t b2 = (size_t)p2 * 128, b3 = (size_t)p3 * 128;
            uint2 uA0 = hp[b0 + lane],      uA1 = hp[b0 + 32 + lane];
            uint2 uA2 = hp[b0 + 64 + lane], uA3 = hp[b0 + 96 + lane];
            uint2 uB0 = hp[b1 + lane],      uB1 = hp[b1 + 32 + lane];
            uint2 uB2 = hp[b1 + 64 + lane], uB3 = hp[b1 + 96 + lane];
            uint2 uC0 = hp[b2 + lane],      uC1 = hp[b2 + 32 + lane];
            uint2 uC2 = hp[b2 + 64 + lane], uC3 = hp[b2 + 96 + lane];
            uint2 uD0 = hp[b3 + lane],      uD1 = hp[b3 + 32 + lane];
            uint2 uD2 = hp[b3 + 64 + lane], uD3 = hp[b3 + 96 + lane];
            acc_h4(a0, uA0, w0.x); acc_h4(a1, uA1, w0.y); acc_h4(a2, uA2, w0.z); acc_h4(a3, uA3, w0.w);
            acc_h4(a0, uB0, w1.x); acc_h4(a1, uB1, w1.y); acc_h4(a2, uB2, w1.z); acc_h4(a3, uB3, w1.w);
            acc_h4(a0, uC0, w2.x); acc_h4(a1, uC1, w2.y); acc_h4(a2, uC2, w2.z); acc_h4(a3, uC3, w2.w);
            acc_h4(a0, uD0, w3.x); acc_h4(a1, uD1, w3.y); acc_h4(a2, uD2, w3.z); acc_h4(a3, uD3, w3.w);
        }
        for (; j < cnt; ++j) {
            int p = s_idx[wp][j];
            float4 w = s_w[wp][j];
            size_t base = (size_t)p * 128;
            uint2 u0 = hp[base + lane];
            uint2 u1 = hp[base + 32 + lane];
            uint2 u2 = hp[base + 64 + lane];
            uint2 u3 = hp[base + 96 + lane];
            acc_h4(a0, u0, w.x); acc_h4(a1, u1, w.y);
            acc_h4(a2, u2, w.z); acc_h4(a3, u3, w.w);
        }
        __syncwarp();
    }
#pragma unroll
    for (int o = 16; o > 0; o >>= 1) {
        d0 += __shfl_xor_sync(0xffffffffu, d0, o);
        d1 += __shfl_xor_sync(0xffffffffu, d1, o);
        d2 += __shfl_xor_sync(0xffffffffu, d2, o);
        d3 += __shfl_xor_sync(0xffffffffu, d3, o);
    }
    float4 inv = make_float4(1.f / (d0 + 1e-16f), 1.f / (d1 + 1e-16f),
                             1.f / (d2 + 1e-16f), 1.f / (d3 + 1e-16f));

    float4 bb = ((const float4*)bias)[lane];
    float4 o;
    o.x = 0.25f * (a0.x * inv.x + a1.x * inv.y + a2.x * inv.z + a3.x * inv.w) + bb.x;
    o.y = 0.25f * (a0.y * inv.x + a1.y * inv.y + a2.y * inv.z + a3.y * inv.w) + bb.y;
    o.z = 0.25f * (a0.z * inv.x + a1.z * inv.y + a2.z * inv.z + a3.z * inv.w) + bb.z;
    o.w = 0.25f * (a0.w * inv.x + a1.w * inv.y + a2.w * inv.z + a3.w * inv.w) + bb.w;
    ((float4*)g_t)[(size_t)n * 32 + lane] = o;

    int c = lane * 4;
    atomicAdd(&s_sum[c + 0], o.x); atomicAdd(&s_sq[c + 0], o.x * o.x);
    atomicAdd(&s_sum[c + 1], o.y); atomicAdd(&s_sq[c + 1], o.y * o.y);
    atomicAdd(&s_sum[c + 2], o.z); atomicAdd(&s_sq[c + 2], o.z * o.z);
    atomicAdd(&s_sum[c + 3], o.w); atomicAdd(&s_sq[c + 3], o.w * o.w);
    __syncthreads();
    if (tid < CC) {
        atomicAdd(&bnsum[tid], s_sum[tid]);
        atomicAdd(&bnsq[tid], s_sq[tid]);
    }
}

// ---------------- launch ----------------
extern "C" void kernel_launch(void* const* d_in, const int* in_sizes, int n_in,
                              void* d_out, int out_size)
{
    const float* x   = (const float*)d_in[0];
    const void*  ei  = d_in[1];
    const float* W1  = (const float*)d_in[2];
    const float* as1 = (const float*)d_in[3];
    const float* ad1 = (const float*)d_in[4];
    const float* b1  = (const float*)d_in[5];
    const float* g1  = (const float*)d_in[6];
    const float* be1 = (const float*)d_in[7];
    const float* W2  = (const float*)d_in[8];
    const float* as2 = (const float*)d_in[9];
    const float* ad2 = (const float*)d_in[10];
    const float* b2  = (const float*)d_in[11];
    const float* g2  = (const float*)d_in[12];
    const float* be2 = (const float*)d_in[13];
    const float* Wf  = (const float*)d_in[14];
    const float* bf  = (const float*)d_in[15];
    int E = in_sizes[1] / 2;

    __half* phh = nullptr;
    float *pt = nullptr, *psA = nullptr, *pqA = nullptr, *psB = nullptr, *pqB = nullptr;
    cudaGetSymbolAddress((void**)&phh, g_hh);
    cudaGetSymbolAddress((void**)&pt, g_t);
    cudaGetSymbolAddress((void**)&psA, g_bnsumA);
    cudaGetSymbolAddress((void**)&pqA, g_bnsqA);
    cudaGetSymbolAddress((void**)&psB, g_bnsumB);
    cudaGetSymbolAddress((void**)&pqB, g_bnsqB);
    float* out = (float*)d_out;

    constexpr int SMEM = 81920;
    cudaFuncSetAttribute(k_gemm_m<256, true, false>,
                         cudaFuncAttributeMaxDynamicSharedMemorySize, SMEM);
    cudaFuncSetAttribute(k_gemm_m<128, true, false>,
                         cudaFuncAttributeMaxDynamicSharedMemorySize, SMEM);
    cudaFuncSetAttribute(k_gemm_m<128, false, true>,
                         cudaFuncAttributeMaxDynamicSharedMemorySize, SMEM);

    // second stream + fork/join events for concurrent CSR build
    cudaStream_t s2;
    cudaStreamCreate(&s2);
    cudaEvent_t e0, e1;
    cudaEventCreateWithFlags(&e0, cudaEventDisableTiming);
    cudaEventCreateWithFlags(&e1, cudaEventDisableTiming);

    // layer 1: conv+prep (+init/detect) on main stream
    k_convprep<false, true><<<8192 + 128, 256>>>(
        (const float4*)x, FIN / 4 - 1, 8192, W1, FIN, HC, nullptr, nullptr,
        nullptr, nullptr, (const unsigned int*)ei);

    // fork: CSR build runs concurrently with layer-1 GEMM
    cudaEventRecord(e0, 0);
    cudaStreamWaitEvent(s2, e0, 0);
    k_hist<<<(E + 255) / 256, 256, 0, s2>>>(ei, E);
    k_scanA<<<128, 256, 0, s2>>>();
    k_scan3<<<128, 256, 0, s2>>>();
    k_scatter<<<(E + NN + 255) / 256, 256, 0, s2>>>(ei, E);
    cudaEventRecord(e1, s2);

    k_gemm_m<256, true, false><<<dim3(4, 256), 256, SMEM>>>(nullptr, HC, as1, ad1, nullptr);

    // join: aggr needs both CSR and gemm1 results
    cudaStreamWaitEvent(0, e1, 0);
    k_aggr<<<4096, 256>>>(phh, b1, psA, pqA);

    // layer 2
    k_convprep<true, false><<<4096 + 64, 256>>>(
        (const float4*)pt, CC / 4 - 1, 4096, W2, CC, HC, g1, be1, psA, pqA, nullptr);
    k_gemm_m<128, true, false><<<dim3(4, 256), 256, SMEM>>>(nullptr, HC, as2, ad2, nullptr);
    k_aggr<<<4096, 256>>>(phh, b2, psB, pqB);

    // final linear (fp32 out)
    k_convprep<true, false><<<4096 + 16, 256>>>(
        (const float4*)pt, CC / 4 - 1, 4096, Wf, CC, CC, g2, be2, psB, pqB, nullptr);
    k_gemm_m<128, false, true><<<dim3(1, 256), 256, SMEM>>>(out, CC, nullptr, nullptr, bf);
}